// round 12
// baseline (speedup 1.0000x reference)
#include <cuda_runtime.h>
#include <cuda_fp16.h>
#include <cstdint>

#define BATCH 4
#define SEQ   4096
#define EMB   1024
#define HD    64
#define MTOT  (BATCH * SEQ)
#define MAXCHUNK 8

// ---------------- device scratch (no allocations allowed) ----------------
__device__ __align__(16) __half g_Qh [(size_t)MTOT * HD];            // [t][h], qscale folded
__device__ __align__(16) __half g_Kh [(size_t)MTOT * HD];            // [t][h]
__device__ __align__(16) __half g_Vth[(size_t)BATCH * HD * SEQ];     // [b][h][t] (transposed)
__device__ __align__(16) float  g_Wt [3 * HD * EMB];                 // [t][h][k]
__device__ __align__(16) float  g_Op [MAXCHUNK][(size_t)MTOT * HD];  // partial O
__device__ __align__(16) float  g_lp [MAXCHUNK][MTOT];               // partial l

// ---------------- helpers ----------------
__device__ __forceinline__ uint32_t pk(float lo, float hi) {
    __half2 h = __floats2half2_rn(lo, hi);
    return *(uint32_t*)&h;
}
__device__ __forceinline__ uint32_t h2ex2(uint32_t x) {
    uint32_t y; asm("ex2.approx.f16x2 %0, %1;" : "=r"(y) : "r"(x)); return y;
}
__device__ __forceinline__ uint32_t smem_u32(const void* p) {
    uint32_t a;
    asm("{ .reg .u64 t; cvta.to.shared.u64 t, %1; cvt.u32.u64 %0, t; }" : "=r"(a) : "l"(p));
    return a;
}
__device__ __forceinline__ void cpa16(uint32_t dst, const void* src) {
    asm volatile("cp.async.cg.shared.global [%0], [%1], 16;" :: "r"(dst), "l"(src) : "memory");
}
#define CP_COMMIT() asm volatile("cp.async.commit_group;" ::: "memory")
#define CP_WAIT(n)  asm volatile("cp.async.wait_group %0;" :: "n"(n) : "memory")

// D(f32) += A(16x16 f16, row) * B(16x8 f16, col)
__device__ __forceinline__ void mma16(float* d,
                                      uint32_t a0, uint32_t a1, uint32_t a2, uint32_t a3,
                                      uint32_t b0, uint32_t b1) {
    asm volatile(
        "mma.sync.aligned.m16n8k16.row.col.f32.f16.f16.f32 "
        "{%0,%1,%2,%3}, {%4,%5,%6,%7}, {%8,%9}, {%0,%1,%2,%3};"
        : "+f"(d[0]), "+f"(d[1]), "+f"(d[2]), "+f"(d[3])
        : "r"(a0), "r"(a1), "r"(a2), "r"(a3), "r"(b0), "r"(b1));
}
// D(f16x2[2]) += A(16x16 f16, row) * B(16x8 f16, col)  -- f16 accum (S only)
__device__ __forceinline__ void mma16h(uint32_t* d,
                                       uint32_t a0, uint32_t a1, uint32_t a2, uint32_t a3,
                                       uint32_t b0, uint32_t b1) {
    asm volatile(
        "mma.sync.aligned.m16n8k16.row.col.f16.f16.f16.f16 "
        "{%0,%1}, {%2,%3,%4,%5}, {%6,%7}, {%0,%1};"
        : "+r"(d[0]), "+r"(d[1])
        : "r"(a0), "r"(a1), "r"(a2), "r"(a3), "r"(b0), "r"(b1));
}

// =====================================================================
// Kernel 0: W transpose -> g_Wt[t][h][k]; fold (1/sqrt(E))*log2(e) into Wq.
// =====================================================================
__global__ __launch_bounds__(256) void wtrans_kernel(const float* __restrict__ Wk,
                                                     const float* __restrict__ Wq,
                                                     const float* __restrict__ Wv) {
    __shared__ float tile[64][65];
    const int t = blockIdx.x;
    const float* W = (t == 0) ? Wq : (t == 1) ? Wk : Wv;
    const float s = (t == 0) ? 0.03125f * 1.44269504088896340736f : 1.0f;
    const int k0 = blockIdx.y * 64;
    const int tid = threadIdx.x;
    for (int i = tid; i < 1024; i += 256) {
        int r = i >> 4, c = (i & 15) << 2;
        float4 v = *(const float4*)&W[(size_t)(k0 + r) * HD + c];
        tile[r][c] = v.x; tile[r][c + 1] = v.y; tile[r][c + 2] = v.z; tile[r][c + 3] = v.w;
    }
    __syncthreads();
    for (int i = tid; i < 4096; i += 256) {
        int h = i >> 6, kk = i & 63;
        g_Wt[(size_t)t * HD * EMB + (size_t)h * EMB + k0 + kk] = tile[kk][h] * s;
    }
}

// =====================================================================
// Kernel 1: projection via mma.sync fp16, f32 accumulators (precision-
// critical: 64-step accumulation chain).  grid(3, MTOT/128).
// =====================================================================
#define HPAD 36
#define QK_XW (128 * HPAD)
#define QK_WORDS (QK_XW + 64 * HPAD)        // 6912 words = 27648 B

__global__ __launch_bounds__(256, 3) void qkv_kernel(const float* __restrict__ x) {
    extern __shared__ uint32_t smq[];
    uint32_t* Xs = smq;
    uint32_t* Ws = smq + QK_XW;
    const int t  = blockIdx.x;
    const int m0 = blockIdx.y * 128;
    const int tid = threadIdx.x, w = tid >> 5, lane = tid & 31;
    const int g = lane >> 2, tig = lane & 3;
    const float* Wt = g_Wt + (size_t)t * HD * EMB;

    float o[8][4];
#pragma unroll
    for (int n = 0; n < 8; n++)
#pragma unroll
        for (int j = 0; j < 4; j++) o[n][j] = 0.f;

    for (int kc = 0; kc < EMB; kc += 64) {
        __syncthreads();
        for (int i = tid; i < 2048; i += 256) {         // x chunk 128x64 -> fp16
            int r = i >> 4, c4 = i & 15;
            float4 v = *(const float4*)&x[(size_t)(m0 + r) * EMB + kc + c4 * 4];
            Xs[r * HPAD + c4 * 2]     = pk(v.x, v.y);
            Xs[r * HPAD + c4 * 2 + 1] = pk(v.z, v.w);
        }
        for (int i = tid; i < 1024; i += 256) {         // W chunk 64x64 -> fp16
            int r = i >> 4, c4 = i & 15;
            float4 v = *(const float4*)&Wt[(size_t)r * EMB + kc + c4 * 4];
            Ws[r * HPAD + c4 * 2]     = pk(v.x, v.y);
            Ws[r * HPAD + c4 * 2 + 1] = pk(v.z, v.w);
        }
        __syncthreads();
#pragma unroll
        for (int kk = 0; kk < 4; kk++) {
            const int kb = kk << 3;
            const int ra = (w * 16 + g) * HPAD + kb;
            const int rb = ra + 8 * HPAD;
            uint32_t a0 = Xs[ra + tig],     a1 = Xs[rb + tig];
            uint32_t a2 = Xs[ra + tig + 4], a3 = Xs[rb + tig + 4];
#pragma unroll
            for (int n = 0; n < 8; n++) {
                const int wb = (n * 8 + g) * HPAD + kb;
                mma16(o[n], a0, a1, a2, a3, Ws[wb + tig], Ws[wb + tig + 4]);
            }
        }
    }

    const int r1 = m0 + w * 16 + g, r2 = r1 + 8;
    if (t < 2) {
        __half* out = (t == 0) ? g_Qh : g_Kh;
#pragma unroll
        for (int n = 0; n < 8; n++) {
            *(__half2*)&out[(size_t)r1 * HD + n * 8 + 2 * tig] = __floats2half2_rn(o[n][0], o[n][1]);
            *(__half2*)&out[(size_t)r2 * HD + n * 8 + 2 * tig] = __floats2half2_rn(o[n][2], o[n][3]);
        }
    } else {
        const int bb = r1 >> 12;
        const int t1 = r1 & 4095, t2 = t1 + 8;
        __half* vt = g_Vth + (size_t)bb * HD * SEQ;
#pragma unroll
        for (int n = 0; n < 8; n++) {
            const int h0 = n * 8 + 2 * tig;
            vt[(size_t)h0 * SEQ + t1]       = __float2half_rn(o[n][0]);
            vt[(size_t)(h0 + 1) * SEQ + t1] = __float2half_rn(o[n][1]);
            vt[(size_t)h0 * SEQ + t2]       = __float2half_rn(o[n][2]);
            vt[(size_t)(h0 + 1) * SEQ + t2] = __float2half_rn(o[n][3]);
        }
    }
}

// =====================================================================
// Kernel 2: chunked causal flash attention.
// S = QK^T with f16 accumulators (shallow K=64 chain; output IS packed
// fp16 pairs -> direct ex2.f16x2, mask post-exp by AND). l and PV keep
// f32 accumulators. 3-stage cp.async pipeline, one sync per iter.
// =====================================================================
#define KV_BUF (2 * 64 * HPAD)               // 4608 words per stage
#define NSTAGE 3
#define ATT_WORDS (NSTAGE * KV_BUF)

__device__ __forceinline__ void load_kv_async(uint32_t sb, int buf,
                                              const __half* Kg, const __half* Vt,
                                              int n0, int tid) {
    const uint32_t kb = sb + buf * (KV_BUF * 4);
    const uint32_t vb = kb + 64 * HPAD * 4;
#pragma unroll
    for (int it = 0; it < 2; it++) {
        int i = it * 256 + tid;                 // 512 chunks of 16B for K
        int r = i >> 3, c4 = i & 7;
        cpa16(kb + (r * HPAD + c4 * 4) * 4, Kg + (size_t)(n0 + r) * HD + c4 * 8);
    }
#pragma unroll
    for (int it = 0; it < 2; it++) {
        int i = it * 256 + tid;                 // 512 chunks of 16B for V^T
        int r = i >> 3, c4 = i & 7;
        cpa16(vb + (r * HPAD + c4 * 4) * 4, Vt + (size_t)r * SEQ + n0 + c4 * 8);
    }
}

__global__ __launch_bounds__(256, 2) void attn_kernel() {
    extern __shared__ uint32_t smu[];
    const uint32_t sb = smem_u32(smu);

    const int bid = blockIdx.x;
    const int b = bid & 3;
    const int j = bid >> 2;
    int qt = 0, ci = 0;
    {
        int acc = 0;
        for (int q = 31; q >= 0; q--) {           // longest-first
            int nc = (2 * q + 9) >> 3;
            if (j < acc + nc) { qt = q; ci = j - acc; break; }
            acc += nc;
        }
    }
    const int q0 = qt << 7;
    const int blk0 = ci << 3;
    int blk1 = blk0 + 8;
    const int nb = 2 * qt + 2;
    if (blk1 > nb) blk1 = nb;

    const int tid = threadIdx.x, w = tid >> 5, lane = tid & 31;
    const int g = lane >> 2, tig = lane & 3;

    const __half* Qg = g_Qh + ((size_t)b * SEQ + q0) * HD;
    const __half* Kg = g_Kh + (size_t)b * SEQ * HD;
    const __half* Vt = g_Vth + (size_t)b * HD * SEQ;

    // ---- prologue: stage Q through smem once, keep A-frags in registers ----
    for (int i = tid; i < 1024; i += 256) {       // 128 rows x 8 uint4
        int r = i >> 3, c4 = i & 7;
        *(uint4*)&smu[r * HPAD + c4 * 4] = *(const uint4*)&Qg[(size_t)r * HD + c4 * 8];
    }
    __syncthreads();
    uint32_t qa[4][4];
    {
        const int ra = (w * 16 + g) * HPAD;
        const int rb = ra + 8 * HPAD;
#pragma unroll
        for (int kk = 0; kk < 4; kk++) {
            const int kb = kk << 3;
            qa[kk][0] = smu[ra + kb + tig];
            qa[kk][1] = smu[rb + kb + tig];
            qa[kk][2] = smu[ra + kb + tig + 4];
            qa[kk][3] = smu[rb + kb + tig + 4];
        }
    }
    __syncthreads();

    // 3-stage pipeline prologue (one commit per stage; empty commits OK)
    load_kv_async(sb, 0, Kg, Vt, blk0 << 6, tid);
    CP_COMMIT();
    if (blk0 + 1 < blk1) load_kv_async(sb, 1, Kg, Vt, (blk0 + 1) << 6, tid);
    CP_COMMIT();

    float o[8][4];
#pragma unroll
    for (int n = 0; n < 8; n++)
#pragma unroll
        for (int jj = 0; jj < 4; jj++) o[n][jj] = 0.f;
    float lacc[4] = {0.f, 0.f, 0.f, 0.f};
    const uint32_t ONES2 = 0x3C003C00u;          // (1.0h, 1.0h)
    const int grow1 = q0 + w * 16 + g, grow2 = grow1 + 8;

    for (int blk = blk0; blk < blk1; blk++) {
        const int cur = (blk - blk0) % NSTAGE;
        CP_WAIT(1);            // all but newest group done -> stage cur ready
        __syncthreads();       // data visible; stage (cur+2)%3 free for reuse
        if (blk + 2 < blk1) load_kv_async(sb, (cur + 2) % NSTAGE, Kg, Vt, (blk + 2) << 6, tid);
        CP_COMMIT();           // exactly one group per iteration

        const uint32_t* Ks = smu + cur * KV_BUF;
        const uint32_t* Vs = Ks + 64 * HPAD;
        const int n0 = blk << 6;

        // S = Q K^T with f16 accumulators (m16 per warp, n=64, k=64)
        uint32_t s2[8][2];
#pragma unroll
        for (int n = 0; n < 8; n++) { s2[n][0] = 0u; s2[n][1] = 0u; }
#pragma unroll
        for (int kk = 0; kk < 4; kk++) {
            const int kb = kk << 3;
#pragma unroll
            for (int n = 0; n < 8; n++) {
                const int kbn = (n * 8 + g) * HPAD + kb;
                mma16h(s2[n], qa[kk][0], qa[kk][1], qa[kk][2], qa[kk][3],
                       Ks[kbn + tig], Ks[kbn + tig + 4]);
            }
        }

        // exp2 in packed fp16, then mask-by-AND (zero the masked halves).
        uint32_t u1[8], u2[8];
#pragma unroll
        for (int n = 0; n < 8; n++) {
            u1[n] = h2ex2(s2[n][0]);
            u2[n] = h2ex2(s2[n][1]);
        }
        if (blk >= 2 * qt) {
#pragma unroll
            for (int n = 0; n < 8; n++) {
                const int cb = n0 + n * 8 + 2 * tig;   // even column index
                const int d1 = grow1 - cb;             // <0: both masked, 0: hi masked
                const int d2 = grow2 - cb;
                u1[n] &= (d1 < 0) ? 0u : ((d1 == 0) ? 0x0000FFFFu : 0xFFFFFFFFu);
                u2[n] &= (d2 < 0) ? 0u : ((d2 == 0) ? 0x0000FFFFu : 0xFFFFFFFFu);
            }
        }

        // l accumulation (f32 ones-MMA) + O += P V (f32 accum)
#pragma unroll
        for (int kk = 0; kk < 4; kk++) {
            const uint32_t a0 = u1[2 * kk],     a1 = u2[2 * kk];
            const uint32_t a2 = u1[2 * kk + 1], a3 = u2[2 * kk + 1];
            mma16(lacc, a0, a1, a2, a3, ONES2, ONES2);   // row sums (exact, f32)
            const int kb = kk << 3;
#pragma unroll
            for (int hh = 0; hh < 8; hh++) {
                const int vr = (hh * 8 + g) * HPAD + kb;
                mma16(o[hh], a0, a1, a2, a3, Vs[vr + tig], Vs[vr + tig + 4]);
            }
        }
    }

    // lacc[0] = full row1 sum, lacc[2] = full row2 sum (k summed inside mma)
    const size_t r1 = (size_t)b * SEQ + q0 + w * 16 + g, r2 = r1 + 8;
    float* dst = &g_Op[ci][0];
#pragma unroll
    for (int hh = 0; hh < 8; hh++) {
        *(float2*)&dst[r1 * HD + hh * 8 + 2 * tig] = make_float2(o[hh][0], o[hh][1]);
        *(float2*)&dst[r2 * HD + hh * 8 + 2 * tig] = make_float2(o[hh][2], o[hh][3]);
    }
    if (tig == 0) { g_lp[ci][r1] = lacc[0]; g_lp[ci][r2] = lacc[2]; }
}

// =====================================================================
// Kernel 3: merge partial slabs and normalize.
// =====================================================================
__global__ __launch_bounds__(256) void merge_kernel(float* __restrict__ out) {
    const int idx = blockIdx.x * 256 + threadIdx.x;   // float4 index
    const int m = idx >> 4;
    const int qt = (m & (SEQ - 1)) >> 7;
    const int nc = (2 * qt + 9) >> 3;
    float4 a = ((const float4*)&g_Op[0][0])[idx];
    float l = g_lp[0][m];
    for (int c = 1; c < nc; c++) {
        float4 t = ((const float4*)&g_Op[c][0])[idx];
        a.x += t.x; a.y += t.y; a.z += t.z; a.w += t.w;
        l += g_lp[c][m];
    }
    const float inv = 1.f / l;
    ((float4*)out)[idx] = make_float4(a.x * inv, a.y * inv, a.z * inv, a.w * inv);
}

// =====================================================================
extern "C" void kernel_launch(void* const* d_in, const int* in_sizes, int n_in,
                              void* d_out, int out_size) {
    const float* x  = (const float*)d_in[0];
    const float* Wk = (const float*)d_in[1];
    const float* Wq = (const float*)d_in[2];
    const float* Wv = (const float*)d_in[3];
    float* out = (float*)d_out;

    // Opt-in smem limit (>48KB dynamic smem requires explicit attribute).
    cudaFuncSetAttribute((const void*)attn_kernel,
                         cudaFuncAttributeMaxDynamicSharedMemorySize, ATT_WORDS * 4);

    wtrans_kernel<<<dim3(3, 16), 256>>>(Wk, Wq, Wv);

    const int qkv_smem = QK_WORDS * 4;     // 27648 B
    qkv_kernel<<<dim3(3, MTOT / 128), 256, qkv_smem>>>(x);

    const int attn_smem = ATT_WORDS * 4;   // 55296 B
    attn_kernel<<<576, 256, attn_smem>>>();

    merge_kernel<<<(MTOT * HD / 4) / 256, 256>>>(out);
}

// round 13
// speedup vs baseline: 1.0361x; 1.0361x over previous
#include <cuda_runtime.h>
#include <cuda_fp16.h>
#include <cstdint>

#define BATCH 4
#define SEQ   4096
#define EMB   1024
#define HD    64
#define MTOT  (BATCH * SEQ)
#define MAXCHUNK 8

// ---------------- device scratch (no allocations allowed) ----------------
__device__ __align__(16) __half g_Qh [(size_t)MTOT * HD];            // [t][h], qscale folded
__device__ __align__(16) __half g_Kh [(size_t)MTOT * HD];            // [t][h]
__device__ __align__(16) __half g_Vth[(size_t)BATCH * HD * SEQ];     // [b][h][t] (transposed)
__device__ __align__(16) float  g_Wt [3 * HD * EMB];                 // [t][h][k]
__device__ __align__(16) __half g_Op [MAXCHUNK][(size_t)MTOT * HD];  // partial O (fp16)
__device__ __align__(16) float  g_lp [MAXCHUNK][MTOT];               // partial l

// ---------------- helpers ----------------
__device__ __forceinline__ uint32_t pk(float lo, float hi) {
    __half2 h = __floats2half2_rn(lo, hi);
    return *(uint32_t*)&h;
}
__device__ __forceinline__ uint32_t h2ex2(uint32_t x) {
    uint32_t y; asm("ex2.approx.f16x2 %0, %1;" : "=r"(y) : "r"(x)); return y;
}
__device__ __forceinline__ uint32_t hadd2(uint32_t a, uint32_t b) {
    uint32_t c; asm("add.rn.f16x2 %0, %1, %2;" : "=r"(c) : "r"(a), "r"(b)); return c;
}
__device__ __forceinline__ uint32_t smem_u32(const void* p) {
    uint32_t a;
    asm("{ .reg .u64 t; cvta.to.shared.u64 t, %1; cvt.u32.u64 %0, t; }" : "=r"(a) : "l"(p));
    return a;
}
__device__ __forceinline__ void cpa16(uint32_t dst, const void* src) {
    asm volatile("cp.async.cg.shared.global [%0], [%1], 16;" :: "r"(dst), "l"(src) : "memory");
}
#define CP_COMMIT() asm volatile("cp.async.commit_group;" ::: "memory")
#define CP_WAIT(n)  asm volatile("cp.async.wait_group %0;" :: "n"(n) : "memory")

// D(f32) += A(16x16 f16, row) * B(16x8 f16, col)
__device__ __forceinline__ void mma16(float* d,
                                      uint32_t a0, uint32_t a1, uint32_t a2, uint32_t a3,
                                      uint32_t b0, uint32_t b1) {
    asm volatile(
        "mma.sync.aligned.m16n8k16.row.col.f32.f16.f16.f32 "
        "{%0,%1,%2,%3}, {%4,%5,%6,%7}, {%8,%9}, {%0,%1,%2,%3};"
        : "+f"(d[0]), "+f"(d[1]), "+f"(d[2]), "+f"(d[3])
        : "r"(a0), "r"(a1), "r"(a2), "r"(a3), "r"(b0), "r"(b1));
}
// D(f16x2[2]) += A(16x16 f16, row) * B(16x8 f16, col)  -- f16 accum (S only)
__device__ __forceinline__ void mma16h(uint32_t* d,
                                       uint32_t a0, uint32_t a1, uint32_t a2, uint32_t a3,
                                       uint32_t b0, uint32_t b1) {
    asm volatile(
        "mma.sync.aligned.m16n8k16.row.col.f16.f16.f16.f16 "
        "{%0,%1}, {%2,%3,%4,%5}, {%6,%7}, {%0,%1};"
        : "+r"(d[0]), "+r"(d[1])
        : "r"(a0), "r"(a1), "r"(a2), "r"(a3), "r"(b0), "r"(b1));
}

// =====================================================================
// Kernel 0: W transpose -> g_Wt[t][h][k]; fold (1/sqrt(E))*log2(e) into Wq.
// =====================================================================
__global__ __launch_bounds__(256) void wtrans_kernel(const float* __restrict__ Wk,
                                                     const float* __restrict__ Wq,
                                                     const float* __restrict__ Wv) {
    __shared__ float tile[64][65];
    const int t = blockIdx.x;
    const float* W = (t == 0) ? Wq : (t == 1) ? Wk : Wv;
    const float s = (t == 0) ? 0.03125f * 1.44269504088896340736f : 1.0f;
    const int k0 = blockIdx.y * 64;
    const int tid = threadIdx.x;
    for (int i = tid; i < 1024; i += 256) {
        int r = i >> 4, c = (i & 15) << 2;
        float4 v = *(const float4*)&W[(size_t)(k0 + r) * HD + c];
        tile[r][c] = v.x; tile[r][c + 1] = v.y; tile[r][c + 2] = v.z; tile[r][c + 3] = v.w;
    }
    __syncthreads();
    for (int i = tid; i < 4096; i += 256) {
        int h = i >> 6, kk = i & 63;
        g_Wt[(size_t)t * HD * EMB + (size_t)h * EMB + k0 + kk] = tile[kk][h] * s;
    }
}

// =====================================================================
// Kernel 1: projection via mma.sync fp16, f32 accumulators (precision-
// critical: 64-step accumulation chain).  grid(3, MTOT/128).
// =====================================================================
#define HPAD 36
#define QK_XW (128 * HPAD)
#define QK_WORDS (QK_XW + 64 * HPAD)        // 6912 words = 27648 B

__global__ __launch_bounds__(256, 3) void qkv_kernel(const float* __restrict__ x) {
    extern __shared__ uint32_t smq[];
    uint32_t* Xs = smq;
    uint32_t* Ws = smq + QK_XW;
    const int t  = blockIdx.x;
    const int m0 = blockIdx.y * 128;
    const int tid = threadIdx.x, w = tid >> 5, lane = tid & 31;
    const int g = lane >> 2, tig = lane & 3;
    const float* Wt = g_Wt + (size_t)t * HD * EMB;

    float o[8][4];
#pragma unroll
    for (int n = 0; n < 8; n++)
#pragma unroll
        for (int j = 0; j < 4; j++) o[n][j] = 0.f;

    for (int kc = 0; kc < EMB; kc += 64) {
        __syncthreads();
        for (int i = tid; i < 2048; i += 256) {         // x chunk 128x64 -> fp16
            int r = i >> 4, c4 = i & 15;
            float4 v = *(const float4*)&x[(size_t)(m0 + r) * EMB + kc + c4 * 4];
            Xs[r * HPAD + c4 * 2]     = pk(v.x, v.y);
            Xs[r * HPAD + c4 * 2 + 1] = pk(v.z, v.w);
        }
        for (int i = tid; i < 1024; i += 256) {         // W chunk 64x64 -> fp16
            int r = i >> 4, c4 = i & 15;
            float4 v = *(const float4*)&Wt[(size_t)r * EMB + kc + c4 * 4];
            Ws[r * HPAD + c4 * 2]     = pk(v.x, v.y);
            Ws[r * HPAD + c4 * 2 + 1] = pk(v.z, v.w);
        }
        __syncthreads();
#pragma unroll
        for (int kk = 0; kk < 4; kk++) {
            const int kb = kk << 3;
            const int ra = (w * 16 + g) * HPAD + kb;
            const int rb = ra + 8 * HPAD;
            uint32_t a0 = Xs[ra + tig],     a1 = Xs[rb + tig];
            uint32_t a2 = Xs[ra + tig + 4], a3 = Xs[rb + tig + 4];
#pragma unroll
            for (int n = 0; n < 8; n++) {
                const int wb = (n * 8 + g) * HPAD + kb;
                mma16(o[n], a0, a1, a2, a3, Ws[wb + tig], Ws[wb + tig + 4]);
            }
        }
    }

    const int r1 = m0 + w * 16 + g, r2 = r1 + 8;
    if (t < 2) {
        __half* out = (t == 0) ? g_Qh : g_Kh;
#pragma unroll
        for (int n = 0; n < 8; n++) {
            *(__half2*)&out[(size_t)r1 * HD + n * 8 + 2 * tig] = __floats2half2_rn(o[n][0], o[n][1]);
            *(__half2*)&out[(size_t)r2 * HD + n * 8 + 2 * tig] = __floats2half2_rn(o[n][2], o[n][3]);
        }
    } else {
        const int bb = r1 >> 12;
        const int t1 = r1 & 4095, t2 = t1 + 8;
        __half* vt = g_Vth + (size_t)bb * HD * SEQ;
#pragma unroll
        for (int n = 0; n < 8; n++) {
            const int h0 = n * 8 + 2 * tig;
            vt[(size_t)h0 * SEQ + t1]       = __float2half_rn(o[n][0]);
            vt[(size_t)(h0 + 1) * SEQ + t1] = __float2half_rn(o[n][1]);
            vt[(size_t)h0 * SEQ + t2]       = __float2half_rn(o[n][2]);
            vt[(size_t)(h0 + 1) * SEQ + t2] = __float2half_rn(o[n][3]);
        }
    }
}

// =====================================================================
// Kernel 2: chunked causal flash attention.
// S = QK^T with f16 accumulators -> direct ex2.f16x2, mask post-exp by
// AND. l via lane-wise HADD2 trees (FMA pipe) instead of ones-MMA.
// Fully-masked warps skip S/exp/PV on the diagonal+1 block.
// PV keeps f32 accum. 3-stage cp.async pipeline, one sync per iter.
// =====================================================================
#define KV_BUF (2 * 64 * HPAD)               // 4608 words per stage
#define NSTAGE 3
#define ATT_WORDS (NSTAGE * KV_BUF)

__device__ __forceinline__ void load_kv_async(uint32_t sb, int buf,
                                              const __half* Kg, const __half* Vt,
                                              int n0, int tid) {
    const uint32_t kb = sb + buf * (KV_BUF * 4);
    const uint32_t vb = kb + 64 * HPAD * 4;
#pragma unroll
    for (int it = 0; it < 2; it++) {
        int i = it * 256 + tid;                 // 512 chunks of 16B for K
        int r = i >> 3, c4 = i & 7;
        cpa16(kb + (r * HPAD + c4 * 4) * 4, Kg + (size_t)(n0 + r) * HD + c4 * 8);
    }
#pragma unroll
    for (int it = 0; it < 2; it++) {
        int i = it * 256 + tid;                 // 512 chunks of 16B for V^T
        int r = i >> 3, c4 = i & 7;
        cpa16(vb + (r * HPAD + c4 * 4) * 4, Vt + (size_t)r * SEQ + n0 + c4 * 8);
    }
}

__global__ __launch_bounds__(256, 2) void attn_kernel() {
    extern __shared__ uint32_t smu[];
    const uint32_t sb = smem_u32(smu);

    const int bid = blockIdx.x;
    const int b = bid & 3;
    const int j = bid >> 2;
    int qt = 0, ci = 0;
    {
        int acc = 0;
        for (int q = 31; q >= 0; q--) {           // longest-first
            int nc = (2 * q + 9) >> 3;
            if (j < acc + nc) { qt = q; ci = j - acc; break; }
            acc += nc;
        }
    }
    const int q0 = qt << 7;
    const int blk0 = ci << 3;
    int blk1 = blk0 + 8;
    const int nb = 2 * qt + 2;
    if (blk1 > nb) blk1 = nb;

    const int tid = threadIdx.x, w = tid >> 5, lane = tid & 31;
    const int g = lane >> 2, tig = lane & 3;

    const __half* Qg = g_Qh + ((size_t)b * SEQ + q0) * HD;
    const __half* Kg = g_Kh + (size_t)b * SEQ * HD;
    const __half* Vt = g_Vth + (size_t)b * HD * SEQ;

    // ---- prologue: stage Q through smem once, keep A-frags in registers ----
    for (int i = tid; i < 1024; i += 256) {       // 128 rows x 8 uint4
        int r = i >> 3, c4 = i & 7;
        *(uint4*)&smu[r * HPAD + c4 * 4] = *(const uint4*)&Qg[(size_t)r * HD + c4 * 8];
    }
    __syncthreads();
    uint32_t qa[4][4];
    {
        const int ra = (w * 16 + g) * HPAD;
        const int rb = ra + 8 * HPAD;
#pragma unroll
        for (int kk = 0; kk < 4; kk++) {
            const int kb = kk << 3;
            qa[kk][0] = smu[ra + kb + tig];
            qa[kk][1] = smu[rb + kb + tig];
            qa[kk][2] = smu[ra + kb + tig + 4];
            qa[kk][3] = smu[rb + kb + tig + 4];
        }
    }
    __syncthreads();

    // 3-stage pipeline prologue (one commit per stage; empty commits OK)
    load_kv_async(sb, 0, Kg, Vt, blk0 << 6, tid);
    CP_COMMIT();
    if (blk0 + 1 < blk1) load_kv_async(sb, 1, Kg, Vt, (blk0 + 1) << 6, tid);
    CP_COMMIT();

    float o[8][4];
#pragma unroll
    for (int n = 0; n < 8; n++)
#pragma unroll
        for (int jj = 0; jj < 4; jj++) o[n][jj] = 0.f;
    float l1 = 0.f, l2 = 0.f;
    const int grow1 = q0 + w * 16 + g, grow2 = grow1 + 8;
    const int wrow_max = q0 + w * 16 + 15;        // warp-uniform last row

    for (int blk = blk0; blk < blk1; blk++) {
        const int cur = (blk - blk0) % NSTAGE;
        CP_WAIT(1);            // all but newest group done -> stage cur ready
        __syncthreads();       // data visible; stage (cur+2)%3 free for reuse
        if (blk + 2 < blk1) load_kv_async(sb, (cur + 2) % NSTAGE, Kg, Vt, (blk + 2) << 6, tid);
        CP_COMMIT();           // exactly one group per iteration

        const int n0 = blk << 6;
        if (n0 > wrow_max) continue;   // fully-masked warp: P==0, nothing to do

        const uint32_t* Ks = smu + cur * KV_BUF;
        const uint32_t* Vs = Ks + 64 * HPAD;

        // S = Q K^T with f16 accumulators (m16 per warp, n=64, k=64)
        uint32_t s2[8][2];
#pragma unroll
        for (int n = 0; n < 8; n++) { s2[n][0] = 0u; s2[n][1] = 0u; }
#pragma unroll
        for (int kk = 0; kk < 4; kk++) {
            const int kb = kk << 3;
#pragma unroll
            for (int n = 0; n < 8; n++) {
                const int kbn = (n * 8 + g) * HPAD + kb;
                mma16h(s2[n], qa[kk][0], qa[kk][1], qa[kk][2], qa[kk][3],
                       Ks[kbn + tig], Ks[kbn + tig + 4]);
            }
        }

        // exp2 in packed fp16, then mask-by-AND (zero the masked halves).
        uint32_t u1[8], u2[8];
#pragma unroll
        for (int n = 0; n < 8; n++) {
            u1[n] = h2ex2(s2[n][0]);
            u2[n] = h2ex2(s2[n][1]);
        }
        if (blk >= 2 * qt) {
#pragma unroll
            for (int n = 0; n < 8; n++) {
                const int cb = n0 + n * 8 + 2 * tig;   // even column index
                const int d1 = grow1 - cb;             // <0: both masked, 0: hi masked
                const int d2 = grow2 - cb;
                u1[n] &= (d1 < 0) ? 0u : ((d1 == 0) ? 0x0000FFFFu : 0xFFFFFFFFu);
                u2[n] &= (d2 < 0) ? 0u : ((d2 == 0) ? 0x0000FFFFu : 0xFFFFFFFFu);
            }
        }

        // l accumulation via lane-wise HADD2 trees (FMA pipe, frees tensor)
        {
            uint32_t t1 = hadd2(hadd2(hadd2(u1[0], u1[1]), hadd2(u1[2], u1[3])),
                                hadd2(hadd2(u1[4], u1[5]), hadd2(u1[6], u1[7])));
            uint32_t t2 = hadd2(hadd2(hadd2(u2[0], u2[1]), hadd2(u2[2], u2[3])),
                                hadd2(hadd2(u2[4], u2[5]), hadd2(u2[6], u2[7])));
            __half2 h1 = *(__half2*)&t1;
            __half2 h2 = *(__half2*)&t2;
            l1 += __half2float(__low2half(h1)) + __half2float(__high2half(h1));
            l2 += __half2float(__low2half(h2)) + __half2float(__high2half(h2));
        }

        // O += P V (f32 accum)
#pragma unroll
        for (int kk = 0; kk < 4; kk++) {
            const uint32_t a0 = u1[2 * kk],     a1 = u2[2 * kk];
            const uint32_t a2 = u1[2 * kk + 1], a3 = u2[2 * kk + 1];
            const int kb = kk << 3;
#pragma unroll
            for (int hh = 0; hh < 8; hh++) {
                const int vr = (hh * 8 + g) * HPAD + kb;
                mma16(o[hh], a0, a1, a2, a3, Vs[vr + tig], Vs[vr + tig + 4]);
            }
        }
    }

    // reduce l across the quad (cols are spread over tig)
    l1 += __shfl_xor_sync(0xffffffffu, l1, 1);
    l1 += __shfl_xor_sync(0xffffffffu, l1, 2);
    l2 += __shfl_xor_sync(0xffffffffu, l2, 1);
    l2 += __shfl_xor_sync(0xffffffffu, l2, 2);

    const size_t r1 = (size_t)b * SEQ + q0 + w * 16 + g, r2 = r1 + 8;
    __half* dst = &g_Op[ci][0];
#pragma unroll
    for (int hh = 0; hh < 8; hh++) {
        *(__half2*)&dst[r1 * HD + hh * 8 + 2 * tig] = __floats2half2_rn(o[hh][0], o[hh][1]);
        *(__half2*)&dst[r2 * HD + hh * 8 + 2 * tig] = __floats2half2_rn(o[hh][2], o[hh][3]);
    }
    if (tig == 0) { g_lp[ci][r1] = l1; g_lp[ci][r2] = l2; }
}

// =====================================================================
// Kernel 3: merge fp16 partial slabs and normalize (f32 math).
// =====================================================================
__global__ __launch_bounds__(256) void merge_kernel(float* __restrict__ out) {
    const int idx = blockIdx.x * 256 + threadIdx.x;   // group of 4 elements
    const int m = idx >> 4;
    const int qt = (m & (SEQ - 1)) >> 7;
    const int nc = (2 * qt + 9) >> 3;
    uint2 raw = ((const uint2*)&g_Op[0][0])[idx];
    float2 p0 = __half22float2(*(__half2*)&raw.x);
    float2 p1 = __half22float2(*(__half2*)&raw.y);
    float4 a = make_float4(p0.x, p0.y, p1.x, p1.y);
    float l = g_lp[0][m];
    for (int c = 1; c < nc; c++) {
        uint2 r2 = ((const uint2*)&g_Op[c][0])[idx];
        float2 q0f = __half22float2(*(__half2*)&r2.x);
        float2 q1f = __half22float2(*(__half2*)&r2.y);
        a.x += q0f.x; a.y += q0f.y; a.z += q1f.x; a.w += q1f.y;
        l += g_lp[c][m];
    }
    const float inv = 1.f / l;
    ((float4*)out)[idx] = make_float4(a.x * inv, a.y * inv, a.z * inv, a.w * inv);
}

// =====================================================================
extern "C" void kernel_launch(void* const* d_in, const int* in_sizes, int n_in,
                              void* d_out, int out_size) {
    const float* x  = (const float*)d_in[0];
    const float* Wk = (const float*)d_in[1];
    const float* Wq = (const float*)d_in[2];
    const float* Wv = (const float*)d_in[3];
    float* out = (float*)d_out;

    // Opt-in smem limit (>48KB dynamic smem requires explicit attribute).
    cudaFuncSetAttribute((const void*)attn_kernel,
                         cudaFuncAttributeMaxDynamicSharedMemorySize, ATT_WORDS * 4);

    wtrans_kernel<<<dim3(3, 16), 256>>>(Wk, Wq, Wv);

    const int qkv_smem = QK_WORDS * 4;     // 27648 B
    qkv_kernel<<<dim3(3, MTOT / 128), 256, qkv_smem>>>(x);

    const int attn_smem = ATT_WORDS * 4;   // 55296 B
    attn_kernel<<<576, 256, attn_smem>>>();

    merge_kernel<<<(MTOT * HD / 4) / 256, 256>>>(out);
}

// round 14
// speedup vs baseline: 1.0749x; 1.0374x over previous
#include <cuda_runtime.h>
#include <cuda_fp16.h>
#include <cstdint>

#define BATCH 4
#define SEQ   4096
#define EMB   1024
#define HD    64
#define MTOT  (BATCH * SEQ)
#define MAXCHUNK 8

// ---------------- device scratch (no allocations allowed) ----------------
__device__ __align__(16) __half g_Qh [(size_t)MTOT * HD];            // [t][h], qscale folded
__device__ __align__(16) __half g_Kh [(size_t)MTOT * HD];            // [t][h]
__device__ __align__(16) __half g_Vth[(size_t)BATCH * HD * SEQ];     // [b][h][t] (transposed)
__device__ __align__(16) __half g_Op [MAXCHUNK][(size_t)MTOT * HD];  // partial O (fp16)
__device__ __align__(16) float  g_lp [MAXCHUNK][MTOT];               // partial l

// ---------------- helpers ----------------
__device__ __forceinline__ uint32_t pk(float lo, float hi) {
    __half2 h = __floats2half2_rn(lo, hi);
    return *(uint32_t*)&h;
}
__device__ __forceinline__ uint32_t h2ex2(uint32_t x) {
    uint32_t y; asm("ex2.approx.f16x2 %0, %1;" : "=r"(y) : "r"(x)); return y;
}
__device__ __forceinline__ uint32_t hadd2(uint32_t a, uint32_t b) {
    uint32_t c; asm("add.rn.f16x2 %0, %1, %2;" : "=r"(c) : "r"(a), "r"(b)); return c;
}
__device__ __forceinline__ uint32_t smem_u32(const void* p) {
    uint32_t a;
    asm("{ .reg .u64 t; cvta.to.shared.u64 t, %1; cvt.u32.u64 %0, t; }" : "=r"(a) : "l"(p));
    return a;
}
__device__ __forceinline__ void cpa16(uint32_t dst, const void* src) {
    asm volatile("cp.async.cg.shared.global [%0], [%1], 16;" :: "r"(dst), "l"(src) : "memory");
}
#define CP_COMMIT() asm volatile("cp.async.commit_group;" ::: "memory")
#define CP_WAIT(n)  asm volatile("cp.async.wait_group %0;" :: "n"(n) : "memory")

// B-fragment load from row-major [k][n] smem via hardware transpose
__device__ __forceinline__ void ldsm_x2_trans(uint32_t& b0, uint32_t& b1, uint32_t addr) {
    asm volatile("ldmatrix.sync.aligned.m8n8.x2.trans.shared.b16 {%0,%1}, [%2];"
                 : "=r"(b0), "=r"(b1) : "r"(addr));
}

// D(f32) += A(16x16 f16, row) * B(16x8 f16, col)
__device__ __forceinline__ void mma16(float* d,
                                      uint32_t a0, uint32_t a1, uint32_t a2, uint32_t a3,
                                      uint32_t b0, uint32_t b1) {
    asm volatile(
        "mma.sync.aligned.m16n8k16.row.col.f32.f16.f16.f32 "
        "{%0,%1,%2,%3}, {%4,%5,%6,%7}, {%8,%9}, {%0,%1,%2,%3};"
        : "+f"(d[0]), "+f"(d[1]), "+f"(d[2]), "+f"(d[3])
        : "r"(a0), "r"(a1), "r"(a2), "r"(a3), "r"(b0), "r"(b1));
}
// D(f16x2[2]) += A(16x16 f16, row) * B(16x8 f16, col)  -- f16 accum (S only)
__device__ __forceinline__ void mma16h(uint32_t* d,
                                       uint32_t a0, uint32_t a1, uint32_t a2, uint32_t a3,
                                       uint32_t b0, uint32_t b1) {
    asm volatile(
        "mma.sync.aligned.m16n8k16.row.col.f16.f16.f16.f16 "
        "{%0,%1}, {%2,%3,%4,%5}, {%6,%7}, {%0,%1};"
        : "+r"(d[0]), "+r"(d[1])
        : "r"(a0), "r"(a1), "r"(a2), "r"(a3), "r"(b0), "r"(b1));
}

// =====================================================================
// Kernel 1: projection via mma.sync fp16, f32 accumulators.
// grid(3, MTOT/128).  W read in NATIVE [k][h] layout; B-fragments via
// ldmatrix.trans (no separate transpose kernel). qscale folded into the
// Q epilogue (f32 multiply before fp16 pack).
// =====================================================================
#define HPAD 36
#define QK_XW (128 * HPAD)
#define QK_WORDS (QK_XW + 64 * HPAD)        // 6912 words = 27648 B

__global__ __launch_bounds__(256, 3) void qkv_kernel(const float* __restrict__ x,
                                                     const float* __restrict__ Wq,
                                                     const float* __restrict__ Wk,
                                                     const float* __restrict__ Wv) {
    extern __shared__ uint32_t smq[];
    uint32_t* Xs = smq;
    uint32_t* Ws = smq + QK_XW;              // [k][h] halves, pitch HPAD words
    const int t  = blockIdx.x;
    const int m0 = blockIdx.y * 128;
    const int tid = threadIdx.x, w = tid >> 5, lane = tid & 31;
    const int g = lane >> 2, tig = lane & 3;
    const float* W = (t == 0) ? Wq : (t == 1) ? Wk : Wv;

    // per-lane LDSM row address base (row = lane & 15)
    const uint32_t ws_b = smem_u32(Ws) + (lane & 15) * (HPAD * 4);

    float o[8][4];
#pragma unroll
    for (int n = 0; n < 8; n++)
#pragma unroll
        for (int j = 0; j < 4; j++) o[n][j] = 0.f;

    for (int kc = 0; kc < EMB; kc += 64) {
        __syncthreads();
        for (int i = tid; i < 2048; i += 256) {         // x chunk 128x64 -> fp16
            int r = i >> 4, c4 = i & 15;
            float4 v = *(const float4*)&x[(size_t)(m0 + r) * EMB + kc + c4 * 4];
            Xs[r * HPAD + c4 * 2]     = pk(v.x, v.y);
            Xs[r * HPAD + c4 * 2 + 1] = pk(v.z, v.w);
        }
        for (int i = tid; i < 1024; i += 256) {         // W chunk 64(k)x64(h) natural
            int r = i >> 4, c4 = i & 15;
            float4 v = *(const float4*)&W[(size_t)(kc + r) * HD + c4 * 4];
            Ws[r * HPAD + c4 * 2]     = pk(v.x, v.y);
            Ws[r * HPAD + c4 * 2 + 1] = pk(v.z, v.w);
        }
        __syncthreads();
#pragma unroll
        for (int kk = 0; kk < 4; kk++) {
            const int kb = kk << 3;
            const int ra = (w * 16 + g) * HPAD + kb;
            const int rb = ra + 8 * HPAD;
            uint32_t a0 = Xs[ra + tig],     a1 = Xs[rb + tig];
            uint32_t a2 = Xs[ra + tig + 4], a3 = Xs[rb + tig + 4];
            const uint32_t wrow = ws_b + kk * (16 * HPAD * 4);
#pragma unroll
            for (int n = 0; n < 8; n++) {
                uint32_t b0, b1;
                ldsm_x2_trans(b0, b1, wrow + n * 16);    // cols n*8..n*8+7
                mma16(o[n], a0, a1, a2, a3, b0, b1);
            }
        }
    }

    const int r1 = m0 + w * 16 + g, r2 = r1 + 8;
    if (t < 2) {
        // fold (1/sqrt(E))*log2(e) into Q here
        const float sc = (t == 0) ? 0.0450842200277801f : 1.0f;
        __half* out = (t == 0) ? g_Qh : g_Kh;
#pragma unroll
        for (int n = 0; n < 8; n++) {
            *(__half2*)&out[(size_t)r1 * HD + n * 8 + 2 * tig] =
                __floats2half2_rn(o[n][0] * sc, o[n][1] * sc);
            *(__half2*)&out[(size_t)r2 * HD + n * 8 + 2 * tig] =
                __floats2half2_rn(o[n][2] * sc, o[n][3] * sc);
        }
    } else {
        const int bb = r1 >> 12;
        const int t1 = r1 & 4095, t2 = t1 + 8;
        __half* vt = g_Vth + (size_t)bb * HD * SEQ;
#pragma unroll
        for (int n = 0; n < 8; n++) {
            const int h0 = n * 8 + 2 * tig;
            vt[(size_t)h0 * SEQ + t1]       = __float2half_rn(o[n][0]);
            vt[(size_t)(h0 + 1) * SEQ + t1] = __float2half_rn(o[n][1]);
            vt[(size_t)h0 * SEQ + t2]       = __float2half_rn(o[n][2]);
            vt[(size_t)(h0 + 1) * SEQ + t2] = __float2half_rn(o[n][3]);
        }
    }
}

// =====================================================================
// Kernel 2: chunked causal flash attention.
// S = QK^T f16-accum -> ex2.f16x2, mask post-exp by AND. l via HADD2
// trees. Diagonal blocks skip unneeded column fragments per warp.
// PV f32 accum. 3-stage cp.async pipeline, one sync per iter.
// =====================================================================
#define KV_BUF (2 * 64 * HPAD)               // 4608 words per stage
#define NSTAGE 3
#define ATT_WORDS (NSTAGE * KV_BUF)

__device__ __forceinline__ void load_kv_async(uint32_t sb, int buf,
                                              const __half* Kg, const __half* Vt,
                                              int n0, int tid) {
    const uint32_t kb = sb + buf * (KV_BUF * 4);
    const uint32_t vb = kb + 64 * HPAD * 4;
#pragma unroll
    for (int it = 0; it < 2; it++) {
        int i = it * 256 + tid;                 // 512 chunks of 16B for K
        int r = i >> 3, c4 = i & 7;
        cpa16(kb + (r * HPAD + c4 * 4) * 4, Kg + (size_t)(n0 + r) * HD + c4 * 8);
    }
#pragma unroll
    for (int it = 0; it < 2; it++) {
        int i = it * 256 + tid;                 // 512 chunks of 16B for V^T
        int r = i >> 3, c4 = i & 7;
        cpa16(vb + (r * HPAD + c4 * 4) * 4, Vt + (size_t)r * SEQ + n0 + c4 * 8);
    }
}

__global__ __launch_bounds__(256, 2) void attn_kernel() {
    extern __shared__ uint32_t smu[];
    const uint32_t sb = smem_u32(smu);

    const int bid = blockIdx.x;
    const int b = bid & 3;
    const int j = bid >> 2;
    int qt = 0, ci = 0;
    {
        int acc = 0;
        for (int q = 31; q >= 0; q--) {           // longest-first
            int nc = (2 * q + 9) >> 3;
            if (j < acc + nc) { qt = q; ci = j - acc; break; }
            acc += nc;
        }
    }
    const int q0 = qt << 7;
    const int blk0 = ci << 3;
    int blk1 = blk0 + 8;
    const int nb = 2 * qt + 2;
    if (blk1 > nb) blk1 = nb;

    const int tid = threadIdx.x, w = tid >> 5, lane = tid & 31;
    const int g = lane >> 2, tig = lane & 3;

    const __half* Qg = g_Qh + ((size_t)b * SEQ + q0) * HD;
    const __half* Kg = g_Kh + (size_t)b * SEQ * HD;
    const __half* Vt = g_Vth + (size_t)b * HD * SEQ;

    // ---- prologue: stage Q through smem once, keep A-frags in registers ----
    for (int i = tid; i < 1024; i += 256) {       // 128 rows x 8 uint4
        int r = i >> 3, c4 = i & 7;
        *(uint4*)&smu[r * HPAD + c4 * 4] = *(const uint4*)&Qg[(size_t)r * HD + c4 * 8];
    }
    __syncthreads();
    uint32_t qa[4][4];
    {
        const int ra = (w * 16 + g) * HPAD;
        const int rb = ra + 8 * HPAD;
#pragma unroll
        for (int kk = 0; kk < 4; kk++) {
            const int kb = kk << 3;
            qa[kk][0] = smu[ra + kb + tig];
            qa[kk][1] = smu[rb + kb + tig];
            qa[kk][2] = smu[ra + kb + tig + 4];
            qa[kk][3] = smu[rb + kb + tig + 4];
        }
    }
    __syncthreads();

    // 3-stage pipeline prologue (one commit per stage; empty commits OK)
    load_kv_async(sb, 0, Kg, Vt, blk0 << 6, tid);
    CP_COMMIT();
    if (blk0 + 1 < blk1) load_kv_async(sb, 1, Kg, Vt, (blk0 + 1) << 6, tid);
    CP_COMMIT();

    float o[8][4];
#pragma unroll
    for (int n = 0; n < 8; n++)
#pragma unroll
        for (int jj = 0; jj < 4; jj++) o[n][jj] = 0.f;
    float l1 = 0.f, l2 = 0.f;
    const int grow1 = q0 + w * 16 + g, grow2 = grow1 + 8;
    const int wrow_max = q0 + w * 16 + 15;        // warp-uniform last row

    for (int blk = blk0; blk < blk1; blk++) {
        const int cur = (blk - blk0) % NSTAGE;
        CP_WAIT(1);            // all but newest group done -> stage cur ready
        __syncthreads();       // data visible; stage (cur+2)%3 free for reuse
        if (blk + 2 < blk1) load_kv_async(sb, (cur + 2) % NSTAGE, Kg, Vt, (blk + 2) << 6, tid);
        CP_COMMIT();           // exactly one group per iteration

        const int n0 = blk << 6;
        if (n0 > wrow_max) continue;   // fully-masked warp: P==0, nothing to do

        const uint32_t* Ks = smu + cur * KV_BUF;
        const uint32_t* Vs = Ks + 64 * HPAD;

        uint32_t u1[8], u2[8];

        if (blk < 2 * qt) {
            // ---------- common path: no masking, all fragments ----------
            uint32_t s2[8][2];
#pragma unroll
            for (int n = 0; n < 8; n++) { s2[n][0] = 0u; s2[n][1] = 0u; }
#pragma unroll
            for (int kk = 0; kk < 4; kk++) {
                const int kb = kk << 3;
#pragma unroll
                for (int n = 0; n < 8; n++) {
                    const int kbn = (n * 8 + g) * HPAD + kb;
                    mma16h(s2[n], qa[kk][0], qa[kk][1], qa[kk][2], qa[kk][3],
                           Ks[kbn + tig], Ks[kbn + tig + 4]);
                }
            }
#pragma unroll
            for (int n = 0; n < 8; n++) {
                u1[n] = h2ex2(s2[n][0]);
                u2[n] = h2ex2(s2[n][1]);
            }
#pragma unroll
            for (int kk = 0; kk < 4; kk++) {
                const uint32_t a0 = u1[2 * kk],     a1 = u2[2 * kk];
                const uint32_t a2 = u1[2 * kk + 1], a3 = u2[2 * kk + 1];
                const int kb = kk << 3;
#pragma unroll
                for (int hh = 0; hh < 8; hh++) {
                    const int vr = (hh * 8 + g) * HPAD + kb;
                    mma16(o[hh], a0, a1, a2, a3, Vs[vr + tig], Vs[vr + tig + 4]);
                }
            }
        } else {
            // ---------- diagonal path: fragment-level skip + mask ----------
            const int rem = wrow_max - n0;         // >= 0, warp-uniform
            uint32_t s2[8][2];
#pragma unroll
            for (int n = 0; n < 8; n++) { s2[n][0] = 0u; s2[n][1] = 0u; }
#pragma unroll
            for (int kk = 0; kk < 4; kk++) {
                const int kb = kk << 3;
#pragma unroll
                for (int n = 0; n < 8; n++) {
                    if (n * 8 <= rem) {
                        const int kbn = (n * 8 + g) * HPAD + kb;
                        mma16h(s2[n], qa[kk][0], qa[kk][1], qa[kk][2], qa[kk][3],
                               Ks[kbn + tig], Ks[kbn + tig + 4]);
                    }
                }
            }
#pragma unroll
            for (int n = 0; n < 8; n++) {
                if (n * 8 <= rem) {
                    u1[n] = h2ex2(s2[n][0]);
                    u2[n] = h2ex2(s2[n][1]);
                    const int cb = n0 + n * 8 + 2 * tig;   // even column index
                    const int d1 = grow1 - cb;
                    const int d2 = grow2 - cb;
                    u1[n] &= (d1 < 0) ? 0u : ((d1 == 0) ? 0x0000FFFFu : 0xFFFFFFFFu);
                    u2[n] &= (d2 < 0) ? 0u : ((d2 == 0) ? 0x0000FFFFu : 0xFFFFFFFFu);
                } else {
                    u1[n] = 0u; u2[n] = 0u;
                }
            }
#pragma unroll
            for (int kk = 0; kk < 4; kk++) {
                if (kk * 16 <= rem) {
                    const uint32_t a0 = u1[2 * kk],     a1 = u2[2 * kk];
                    const uint32_t a2 = u1[2 * kk + 1], a3 = u2[2 * kk + 1];
                    const int kb = kk << 3;
#pragma unroll
                    for (int hh = 0; hh < 8; hh++) {
                        const int vr = (hh * 8 + g) * HPAD + kb;
                        mma16(o[hh], a0, a1, a2, a3, Vs[vr + tig], Vs[vr + tig + 4]);
                    }
                }
            }
        }

        // l accumulation via lane-wise HADD2 trees (FMA pipe)
        {
            uint32_t t1 = hadd2(hadd2(hadd2(u1[0], u1[1]), hadd2(u1[2], u1[3])),
                                hadd2(hadd2(u1[4], u1[5]), hadd2(u1[6], u1[7])));
            uint32_t t2 = hadd2(hadd2(hadd2(u2[0], u2[1]), hadd2(u2[2], u2[3])),
                                hadd2(hadd2(u2[4], u2[5]), hadd2(u2[6], u2[7])));
            __half2 h1 = *(__half2*)&t1;
            __half2 h2 = *(__half2*)&t2;
            l1 += __half2float(__low2half(h1)) + __half2float(__high2half(h1));
            l2 += __half2float(__low2half(h2)) + __half2float(__high2half(h2));
        }
    }

    // reduce l across the quad (cols are spread over tig)
    l1 += __shfl_xor_sync(0xffffffffu, l1, 1);
    l1 += __shfl_xor_sync(0xffffffffu, l1, 2);
    l2 += __shfl_xor_sync(0xffffffffu, l2, 1);
    l2 += __shfl_xor_sync(0xffffffffu, l2, 2);

    const size_t r1 = (size_t)b * SEQ + q0 + w * 16 + g, r2 = r1 + 8;
    __half* dst = &g_Op[ci][0];
#pragma unroll
    for (int hh = 0; hh < 8; hh++) {
        *(__half2*)&dst[r1 * HD + hh * 8 + 2 * tig] = __floats2half2_rn(o[hh][0], o[hh][1]);
        *(__half2*)&dst[r2 * HD + hh * 8 + 2 * tig] = __floats2half2_rn(o[hh][2], o[hh][3]);
    }
    if (tig == 0) { g_lp[ci][r1] = l1; g_lp[ci][r2] = l2; }
}

// =====================================================================
// Kernel 3: merge fp16 partial slabs and normalize (f32 math).
// Two independent groups per thread for ILP.
// =====================================================================
__device__ __forceinline__ void merge_one(int idx, float* __restrict__ out) {
    const int m = idx >> 4;
    const int qt = (m & (SEQ - 1)) >> 7;
    const int nc = (2 * qt + 9) >> 3;
    uint2 raw = ((const uint2*)&g_Op[0][0])[idx];
    float2 p0 = __half22float2(*(__half2*)&raw.x);
    float2 p1 = __half22float2(*(__half2*)&raw.y);
    float4 a = make_float4(p0.x, p0.y, p1.x, p1.y);
    float l = g_lp[0][m];
    for (int c = 1; c < nc; c++) {
        uint2 r2 = ((const uint2*)&g_Op[c][0])[idx];
        float2 q0f = __half22float2(*(__half2*)&r2.x);
        float2 q1f = __half22float2(*(__half2*)&r2.y);
        a.x += q0f.x; a.y += q0f.y; a.z += q1f.x; a.w += q1f.y;
        l += g_lp[c][m];
    }
    const float inv = 1.f / l;
    ((float4*)out)[idx] = make_float4(a.x * inv, a.y * inv, a.z * inv, a.w * inv);
}

__global__ __launch_bounds__(256) void merge_kernel(float* __restrict__ out) {
    const int idx = blockIdx.x * 256 + threadIdx.x;   // 0..131071
    merge_one(idx, out);
    merge_one(idx + 131072, out);
}

// =====================================================================
extern "C" void kernel_launch(void* const* d_in, const int* in_sizes, int n_in,
                              void* d_out, int out_size) {
    const float* x  = (const float*)d_in[0];
    const float* Wk = (const float*)d_in[1];
    const float* Wq = (const float*)d_in[2];
    const float* Wv = (const float*)d_in[3];
    float* out = (float*)d_out;

    // Opt-in smem limit (>48KB dynamic smem requires explicit attribute).
    cudaFuncSetAttribute((const void*)attn_kernel,
                         cudaFuncAttributeMaxDynamicSharedMemorySize, ATT_WORDS * 4);

    const int qkv_smem = QK_WORDS * 4;     // 27648 B
    qkv_kernel<<<dim3(3, MTOT / 128), 256, qkv_smem>>>(x, Wq, Wk, Wv);

    const int attn_smem = ATT_WORDS * 4;   // 55296 B
    attn_kernel<<<576, 256, attn_smem>>>();

    merge_kernel<<<512, 256>>>(out);
}

// round 16
// speedup vs baseline: 1.1408x; 1.0613x over previous
#include <cuda_runtime.h>
#include <cuda_fp16.h>
#include <cstdint>

#define BATCH 4
#define SEQ   4096
#define EMB   1024
#define HD    64
#define MTOT  (BATCH * SEQ)
#define MAXCHUNK 8

// ---------------- device scratch (no allocations allowed) ----------------
__device__ __align__(16) __half g_Qh [(size_t)MTOT * HD];            // [t][h], qscale folded
__device__ __align__(16) __half g_Kh [(size_t)MTOT * HD];            // [t][h]
__device__ __align__(16) __half g_Vth[(size_t)BATCH * HD * SEQ];     // [b][h][t] (transposed)
__device__ __align__(16) __half g_Op [MAXCHUNK][(size_t)MTOT * HD];  // partial O (fp16)
__device__ __align__(16) float  g_lp [MAXCHUNK][MTOT];               // partial l

// ---------------- helpers ----------------
__device__ __forceinline__ uint32_t pk(float lo, float hi) {
    __half2 h = __floats2half2_rn(lo, hi);
    return *(uint32_t*)&h;
}
__device__ __forceinline__ uint32_t h2ex2(uint32_t x) {
    uint32_t y; asm("ex2.approx.f16x2 %0, %1;" : "=r"(y) : "r"(x)); return y;
}
__device__ __forceinline__ uint32_t hadd2(uint32_t a, uint32_t b) {
    uint32_t c; asm("add.rn.f16x2 %0, %1, %2;" : "=r"(c) : "r"(a), "r"(b)); return c;
}
__device__ __forceinline__ uint32_t smem_u32(const void* p) {
    uint32_t a;
    asm("{ .reg .u64 t; cvta.to.shared.u64 t, %1; cvt.u32.u64 %0, t; }" : "=r"(a) : "l"(p));
    return a;
}
__device__ __forceinline__ void cpa16(uint32_t dst, const void* src) {
    asm volatile("cp.async.cg.shared.global [%0], [%1], 16;" :: "r"(dst), "l"(src) : "memory");
}
#define CP_COMMIT() asm volatile("cp.async.commit_group;" ::: "memory")
#define CP_WAIT(n)  asm volatile("cp.async.wait_group %0;" :: "n"(n) : "memory")

// B-fragment load from row-major [k][n] smem via hardware transpose
__device__ __forceinline__ void ldsm_x2_trans(uint32_t& b0, uint32_t& b1, uint32_t addr) {
    asm volatile("ldmatrix.sync.aligned.m8n8.x2.trans.shared.b16 {%0,%1}, [%2];"
                 : "=r"(b0), "=r"(b1) : "r"(addr));
}

// D(f32) += A(16x16 f16, row) * B(16x8 f16, col)
__device__ __forceinline__ void mma16(float* d,
                                      uint32_t a0, uint32_t a1, uint32_t a2, uint32_t a3,
                                      uint32_t b0, uint32_t b1) {
    asm volatile(
        "mma.sync.aligned.m16n8k16.row.col.f32.f16.f16.f32 "
        "{%0,%1,%2,%3}, {%4,%5,%6,%7}, {%8,%9}, {%0,%1,%2,%3};"
        : "+f"(d[0]), "+f"(d[1]), "+f"(d[2]), "+f"(d[3])
        : "r"(a0), "r"(a1), "r"(a2), "r"(a3), "r"(b0), "r"(b1));
}
// D(f16x2[2]) += A(16x16 f16, row) * B(16x8 f16, col)  -- f16 accum (S only)
__device__ __forceinline__ void mma16h(uint32_t* d,
                                       uint32_t a0, uint32_t a1, uint32_t a2, uint32_t a3,
                                       uint32_t b0, uint32_t b1) {
    asm volatile(
        "mma.sync.aligned.m16n8k16.row.col.f16.f16.f16.f16 "
        "{%0,%1}, {%2,%3,%4,%5}, {%6,%7}, {%0,%1};"
        : "+r"(d[0]), "+r"(d[1])
        : "r"(a0), "r"(a1), "r"(a2), "r"(a3), "r"(b0), "r"(b1));
}

// =====================================================================
// Kernel 1: projection via mma.sync fp16, f32 accumulators.
// grid(3, MTOT/128). Software-pipelined: next K-chunk prefetched into
// REGISTERS during the MMA phase, stored to the alternate smem buffer,
// ONE __syncthreads per iteration. W read in native [k][h] layout,
// B-fragments via ldmatrix.trans. qscale folded into the Q epilogue.
// =====================================================================
#define HPAD 36
#define QK_XW (128 * HPAD)
#define QK_STAGE (QK_XW + 64 * HPAD)        // 6912 words = 27648 B
#define QK_WORDS (2 * QK_STAGE)             // 55296 B (double buffer)

__global__ __launch_bounds__(256, 2) void qkv_kernel(const float* __restrict__ x,
                                                     const float* __restrict__ Wq,
                                                     const float* __restrict__ Wk,
                                                     const float* __restrict__ Wv) {
    extern __shared__ uint32_t smq[];
    const int t  = blockIdx.x;
    const int m0 = blockIdx.y * 128;
    const int tid = threadIdx.x, w = tid >> 5, lane = tid & 31;
    const int g = lane >> 2, tig = lane & 3;
    const float* W = (t == 0) ? Wq : (t == 1) ? Wk : Wv;

    float4 px[8], pw[4];                     // prefetch registers

    float o[8][4];
#pragma unroll
    for (int n = 0; n < 8; n++)
#pragma unroll
        for (int j = 0; j < 4; j++) o[n][j] = 0.f;

    // ---- prologue: fetch chunk 0, convert+store to buffer 0 ----
#pragma unroll
    for (int it = 0; it < 8; it++) {
        int i = it * 256 + tid, r = i >> 4, c4 = i & 15;
        px[it] = *(const float4*)&x[(size_t)(m0 + r) * EMB + c4 * 4];
    }
#pragma unroll
    for (int it = 0; it < 4; it++) {
        int i = it * 256 + tid, r = i >> 4, c4 = i & 15;
        pw[it] = *(const float4*)&W[(size_t)r * HD + c4 * 4];
    }
    {
        uint32_t* Xs = smq;
        uint32_t* Ws = smq + QK_XW;
#pragma unroll
        for (int it = 0; it < 8; it++) {
            int i = it * 256 + tid, r = i >> 4, c4 = i & 15;
            Xs[r * HPAD + c4 * 2]     = pk(px[it].x, px[it].y);
            Xs[r * HPAD + c4 * 2 + 1] = pk(px[it].z, px[it].w);
        }
#pragma unroll
        for (int it = 0; it < 4; it++) {
            int i = it * 256 + tid, r = i >> 4, c4 = i & 15;
            Ws[r * HPAD + c4 * 2]     = pk(pw[it].x, pw[it].y);
            Ws[r * HPAD + c4 * 2 + 1] = pk(pw[it].z, pw[it].w);
        }
    }
    __syncthreads();

    // ---- pipelined mainloop: one sync per iteration ----
    for (int kci = 0; kci < 16; kci++) {
        const int cur = kci & 1;
        uint32_t* Xs = smq + cur * QK_STAGE;
        uint32_t* Ws = Xs + QK_XW;

        // issue next chunk's global loads early (latency hidden by MMAs)
        if (kci < 15) {
            const int kc = (kci + 1) * 64;
#pragma unroll
            for (int it = 0; it < 8; it++) {
                int i = it * 256 + tid, r = i >> 4, c4 = i & 15;
                px[it] = *(const float4*)&x[(size_t)(m0 + r) * EMB + kc + c4 * 4];
            }
#pragma unroll
            for (int it = 0; it < 4; it++) {
                int i = it * 256 + tid, r = i >> 4, c4 = i & 15;
                pw[it] = *(const float4*)&W[(size_t)(kc + r) * HD + c4 * 4];
            }
        }

        // compute on current buffer
        const uint32_t ws_b = smem_u32(Ws) + (lane & 15) * (HPAD * 4);
#pragma unroll
        for (int kk = 0; kk < 4; kk++) {
            const int kb = kk << 3;
            const int ra = (w * 16 + g) * HPAD + kb;
            const int rb = ra + 8 * HPAD;
            uint32_t a0 = Xs[ra + tig],     a1 = Xs[rb + tig];
            uint32_t a2 = Xs[ra + tig + 4], a3 = Xs[rb + tig + 4];
            const uint32_t wrow = ws_b + kk * (16 * HPAD * 4);
#pragma unroll
            for (int n = 0; n < 8; n++) {
                uint32_t b0, b1;
                ldsm_x2_trans(b0, b1, wrow + n * 16);    // cols n*8..n*8+7
                mma16(o[n], a0, a1, a2, a3, b0, b1);
            }
        }

        // convert+store the prefetched chunk to the OTHER buffer
        // (safe: previous iter's end-sync proved it fully consumed)
        if (kci < 15) {
            uint32_t* Xn = smq + (cur ^ 1) * QK_STAGE;
            uint32_t* Wn = Xn + QK_XW;
#pragma unroll
            for (int it = 0; it < 8; it++) {
                int i = it * 256 + tid, r = i >> 4, c4 = i & 15;
                Xn[r * HPAD + c4 * 2]     = pk(px[it].x, px[it].y);
                Xn[r * HPAD + c4 * 2 + 1] = pk(px[it].z, px[it].w);
            }
#pragma unroll
            for (int it = 0; it < 4; it++) {
                int i = it * 256 + tid, r = i >> 4, c4 = i & 15;
                Wn[r * HPAD + c4 * 2]     = pk(pw[it].x, pw[it].y);
                Wn[r * HPAD + c4 * 2 + 1] = pk(pw[it].z, pw[it].w);
            }
        }
        __syncthreads();
    }

    const int r1 = m0 + w * 16 + g, r2 = r1 + 8;
    if (t < 2) {
        // fold (1/sqrt(E))*log2(e) into Q here
        const float sc = (t == 0) ? 0.0450842200277801f : 1.0f;
        __half* out = (t == 0) ? g_Qh : g_Kh;
#pragma unroll
        for (int n = 0; n < 8; n++) {
            *(__half2*)&out[(size_t)r1 * HD + n * 8 + 2 * tig] =
                __floats2half2_rn(o[n][0] * sc, o[n][1] * sc);
            *(__half2*)&out[(size_t)r2 * HD + n * 8 + 2 * tig] =
                __floats2half2_rn(o[n][2] * sc, o[n][3] * sc);
        }
    } else {
        const int bb = r1 >> 12;
        const int t1 = r1 & 4095, t2 = t1 + 8;
        __half* vt = g_Vth + (size_t)bb * HD * SEQ;
#pragma unroll
        for (int n = 0; n < 8; n++) {
            const int h0 = n * 8 + 2 * tig;
            vt[(size_t)h0 * SEQ + t1]       = __float2half_rn(o[n][0]);
            vt[(size_t)(h0 + 1) * SEQ + t1] = __float2half_rn(o[n][1]);
            vt[(size_t)h0 * SEQ + t2]       = __float2half_rn(o[n][2]);
            vt[(size_t)(h0 + 1) * SEQ + t2] = __float2half_rn(o[n][3]);
        }
    }
}

// =====================================================================
// Kernel 2: chunked causal flash attention.  (unchanged from R13)
// =====================================================================
#define KV_BUF (2 * 64 * HPAD)               // 4608 words per stage
#define NSTAGE 3
#define ATT_WORDS (NSTAGE * KV_BUF)

__device__ __forceinline__ void load_kv_async(uint32_t sb, int buf,
                                              const __half* Kg, const __half* Vt,
                                              int n0, int tid) {
    const uint32_t kb = sb + buf * (KV_BUF * 4);
    const uint32_t vb = kb + 64 * HPAD * 4;
#pragma unroll
    for (int it = 0; it < 2; it++) {
        int i = it * 256 + tid;                 // 512 chunks of 16B for K
        int r = i >> 3, c4 = i & 7;
        cpa16(kb + (r * HPAD + c4 * 4) * 4, Kg + (size_t)(n0 + r) * HD + c4 * 8);
    }
#pragma unroll
    for (int it = 0; it < 2; it++) {
        int i = it * 256 + tid;                 // 512 chunks of 16B for V^T
        int r = i >> 3, c4 = i & 7;
        cpa16(vb + (r * HPAD + c4 * 4) * 4, Vt + (size_t)r * SEQ + n0 + c4 * 8);
    }
}

__global__ __launch_bounds__(256, 2) void attn_kernel() {
    extern __shared__ uint32_t smu[];
    const uint32_t sb = smem_u32(smu);

    const int bid = blockIdx.x;
    const int b = bid & 3;
    const int j = bid >> 2;
    int qt = 0, ci = 0;
    {
        int acc = 0;
        for (int q = 31; q >= 0; q--) {           // longest-first
            int nc = (2 * q + 9) >> 3;
            if (j < acc + nc) { qt = q; ci = j - acc; break; }
            acc += nc;
        }
    }
    const int q0 = qt << 7;
    const int blk0 = ci << 3;
    int blk1 = blk0 + 8;
    const int nb = 2 * qt + 2;
    if (blk1 > nb) blk1 = nb;

    const int tid = threadIdx.x, w = tid >> 5, lane = tid & 31;
    const int g = lane >> 2, tig = lane & 3;

    const __half* Qg = g_Qh + ((size_t)b * SEQ + q0) * HD;
    const __half* Kg = g_Kh + (size_t)b * SEQ * HD;
    const __half* Vt = g_Vth + (size_t)b * HD * SEQ;

    // ---- prologue: stage Q through smem once, keep A-frags in registers ----
    for (int i = tid; i < 1024; i += 256) {       // 128 rows x 8 uint4
        int r = i >> 3, c4 = i & 7;
        *(uint4*)&smu[r * HPAD + c4 * 4] = *(const uint4*)&Qg[(size_t)r * HD + c4 * 8];
    }
    __syncthreads();
    uint32_t qa[4][4];
    {
        const int ra = (w * 16 + g) * HPAD;
        const int rb = ra + 8 * HPAD;
#pragma unroll
        for (int kk = 0; kk < 4; kk++) {
            const int kb = kk << 3;
            qa[kk][0] = smu[ra + kb + tig];
            qa[kk][1] = smu[rb + kb + tig];
            qa[kk][2] = smu[ra + kb + tig + 4];
            qa[kk][3] = smu[rb + kb + tig + 4];
        }
    }
    __syncthreads();

    // 3-stage pipeline prologue (one commit per stage; empty commits OK)
    load_kv_async(sb, 0, Kg, Vt, blk0 << 6, tid);
    CP_COMMIT();
    if (blk0 + 1 < blk1) load_kv_async(sb, 1, Kg, Vt, (blk0 + 1) << 6, tid);
    CP_COMMIT();

    float o[8][4];
#pragma unroll
    for (int n = 0; n < 8; n++)
#pragma unroll
        for (int jj = 0; jj < 4; jj++) o[n][jj] = 0.f;
    float l1 = 0.f, l2 = 0.f;
    const int grow1 = q0 + w * 16 + g, grow2 = grow1 + 8;
    const int wrow_max = q0 + w * 16 + 15;        // warp-uniform last row

    for (int blk = blk0; blk < blk1; blk++) {
        const int cur = (blk - blk0) % NSTAGE;
        CP_WAIT(1);            // all but newest group done -> stage cur ready
        __syncthreads();       // data visible; stage (cur+2)%3 free for reuse
        if (blk + 2 < blk1) load_kv_async(sb, (cur + 2) % NSTAGE, Kg, Vt, (blk + 2) << 6, tid);
        CP_COMMIT();           // exactly one group per iteration

        const int n0 = blk << 6;
        if (n0 > wrow_max) continue;   // fully-masked warp: P==0, nothing to do

        const uint32_t* Ks = smu + cur * KV_BUF;
        const uint32_t* Vs = Ks + 64 * HPAD;

        uint32_t u1[8], u2[8];

        if (blk < 2 * qt) {
            // ---------- common path: no masking, all fragments ----------
            uint32_t s2[8][2];
#pragma unroll
            for (int n = 0; n < 8; n++) { s2[n][0] = 0u; s2[n][1] = 0u; }
#pragma unroll
            for (int kk = 0; kk < 4; kk++) {
                const int kb = kk << 3;
#pragma unroll
                for (int n = 0; n < 8; n++) {
                    const int kbn = (n * 8 + g) * HPAD + kb;
                    mma16h(s2[n], qa[kk][0], qa[kk][1], qa[kk][2], qa[kk][3],
                           Ks[kbn + tig], Ks[kbn + tig + 4]);
                }
            }
#pragma unroll
            for (int n = 0; n < 8; n++) {
                u1[n] = h2ex2(s2[n][0]);
                u2[n] = h2ex2(s2[n][1]);
            }
#pragma unroll
            for (int kk = 0; kk < 4; kk++) {
                const uint32_t a0 = u1[2 * kk],     a1 = u2[2 * kk];
                const uint32_t a2 = u1[2 * kk + 1], a3 = u2[2 * kk + 1];
                const int kb = kk << 3;
#pragma unroll
                for (int hh = 0; hh < 8; hh++) {
                    const int vr = (hh * 8 + g) * HPAD + kb;
                    mma16(o[hh], a0, a1, a2, a3, Vs[vr + tig], Vs[vr + tig + 4]);
                }
            }
        } else {
            // ---------- diagonal path: fragment-level skip + mask ----------
            const int rem = wrow_max - n0;         // >= 0, warp-uniform
            uint32_t s2[8][2];
#pragma unroll
            for (int n = 0; n < 8; n++) { s2[n][0] = 0u; s2[n][1] = 0u; }
#pragma unroll
            for (int kk = 0; kk < 4; kk++) {
                const int kb = kk << 3;
#pragma unroll
                for (int n = 0; n < 8; n++) {
                    if (n * 8 <= rem) {
                        const int kbn = (n * 8 + g) * HPAD + kb;
                        mma16h(s2[n], qa[kk][0], qa[kk][1], qa[kk][2], qa[kk][3],
                               Ks[kbn + tig], Ks[kbn + tig + 4]);
                    }
                }
            }
#pragma unroll
            for (int n = 0; n < 8; n++) {
                if (n * 8 <= rem) {
                    u1[n] = h2ex2(s2[n][0]);
                    u2[n] = h2ex2(s2[n][1]);
                    const int cb = n0 + n * 8 + 2 * tig;   // even column index
                    const int d1 = grow1 - cb;
                    const int d2 = grow2 - cb;
                    u1[n] &= (d1 < 0) ? 0u : ((d1 == 0) ? 0x0000FFFFu : 0xFFFFFFFFu);
                    u2[n] &= (d2 < 0) ? 0u : ((d2 == 0) ? 0x0000FFFFu : 0xFFFFFFFFu);
                } else {
                    u1[n] = 0u; u2[n] = 0u;
                }
            }
#pragma unroll
            for (int kk = 0; kk < 4; kk++) {
                if (kk * 16 <= rem) {
                    const uint32_t a0 = u1[2 * kk],     a1 = u2[2 * kk];
                    const uint32_t a2 = u1[2 * kk + 1], a3 = u2[2 * kk + 1];
                    const int kb = kk << 3;
#pragma unroll
                    for (int hh = 0; hh < 8; hh++) {
                        const int vr = (hh * 8 + g) * HPAD + kb;
                        mma16(o[hh], a0, a1, a2, a3, Vs[vr + tig], Vs[vr + tig + 4]);
                    }
                }
            }
        }

        // l accumulation via lane-wise HADD2 trees (FMA pipe)
        {
            uint32_t t1 = hadd2(hadd2(hadd2(u1[0], u1[1]), hadd2(u1[2], u1[3])),
                                hadd2(hadd2(u1[4], u1[5]), hadd2(u1[6], u1[7])));
            uint32_t t2 = hadd2(hadd2(hadd2(u2[0], u2[1]), hadd2(u2[2], u2[3])),
                                hadd2(hadd2(u2[4], u2[5]), hadd2(u2[6], u2[7])));
            __half2 h1 = *(__half2*)&t1;
            __half2 h2 = *(__half2*)&t2;
            l1 += __half2float(__low2half(h1)) + __half2float(__high2half(h1));
            l2 += __half2float(__low2half(h2)) + __half2float(__high2half(h2));
        }
    }

    // reduce l across the quad (cols are spread over tig)
    l1 += __shfl_xor_sync(0xffffffffu, l1, 1);
    l1 += __shfl_xor_sync(0xffffffffu, l1, 2);
    l2 += __shfl_xor_sync(0xffffffffu, l2, 1);
    l2 += __shfl_xor_sync(0xffffffffu, l2, 2);

    const size_t r1 = (size_t)b * SEQ + q0 + w * 16 + g, r2 = r1 + 8;
    __half* dst = &g_Op[ci][0];
#pragma unroll
    for (int hh = 0; hh < 8; hh++) {
        *(__half2*)&dst[r1 * HD + hh * 8 + 2 * tig] = __floats2half2_rn(o[hh][0], o[hh][1]);
        *(__half2*)&dst[r2 * HD + hh * 8 + 2 * tig] = __floats2half2_rn(o[hh][2], o[hh][3]);
    }
    if (tig == 0) { g_lp[ci][r1] = l1; g_lp[ci][r2] = l2; }
}

// =====================================================================
// Kernel 3: merge fp16 partial slabs and normalize (f32 math).
// Two independent groups per thread for ILP.
// =====================================================================
__device__ __forceinline__ void merge_one(int idx, float* __restrict__ out) {
    const int m = idx >> 4;
    const int qt = (m & (SEQ - 1)) >> 7;
    const int nc = (2 * qt + 9) >> 3;
    uint2 raw = ((const uint2*)&g_Op[0][0])[idx];
    float2 p0 = __half22float2(*(__half2*)&raw.x);
    float2 p1 = __half22float2(*(__half2*)&raw.y);
    float4 a = make_float4(p0.x, p0.y, p1.x, p1.y);
    float l = g_lp[0][m];
    for (int c = 1; c < nc; c++) {
        uint2 r2 = ((const uint2*)&g_Op[c][0])[idx];
        float2 q0f = __half22float2(*(__half2*)&r2.x);
        float2 q1f = __half22float2(*(__half2*)&r2.y);
        a.x += q0f.x; a.y += q0f.y; a.z += q1f.x; a.w += q1f.y;
        l += g_lp[c][m];
    }
    const float inv = 1.f / l;
    ((float4*)out)[idx] = make_float4(a.x * inv, a.y * inv, a.z * inv, a.w * inv);
}

__global__ __launch_bounds__(256) void merge_kernel(float* __restrict__ out) {
    const int idx = blockIdx.x * 256 + threadIdx.x;   // 0..131071
    merge_one(idx, out);
    merge_one(idx + 131072, out);
}

// =====================================================================
extern "C" void kernel_launch(void* const* d_in, const int* in_sizes, int n_in,
                              void* d_out, int out_size) {
    const float* x  = (const float*)d_in[0];
    const float* Wk = (const float*)d_in[1];
    const float* Wq = (const float*)d_in[2];
    const float* Wv = (const float*)d_in[3];
    float* out = (float*)d_out;

    // Opt-in smem limits (>48KB dynamic smem requires explicit attribute).
    cudaFuncSetAttribute((const void*)qkv_kernel,
                         cudaFuncAttributeMaxDynamicSharedMemorySize, QK_WORDS * 4);
    cudaFuncSetAttribute((const void*)attn_kernel,
                         cudaFuncAttributeMaxDynamicSharedMemorySize, ATT_WORDS * 4);

    const int qkv_smem = QK_WORDS * 4;     // 55296 B
    qkv_kernel<<<dim3(3, MTOT / 128), 256, qkv_smem>>>(x, Wq, Wk, Wv);

    const int attn_smem = ATT_WORDS * 4;   // 55296 B
    attn_kernel<<<576, 256, attn_smem>>>();

    merge_kernel<<<512, 256>>>(out);
}

// round 17
// speedup vs baseline: 1.2048x; 1.0562x over previous
#include <cuda_runtime.h>
#include <cuda_fp16.h>
#include <cstdint>

#define BATCH 4
#define SEQ   4096
#define EMB   1024
#define HD    64
#define MTOT  (BATCH * SEQ)
#define MAXCHUNK 8

// ---------------- device scratch (no allocations allowed) ----------------
__device__ __align__(16) __half g_Qh [(size_t)MTOT * HD];            // [t][h], qscale folded
__device__ __align__(16) __half g_Kh [(size_t)MTOT * HD];            // [t][h]
__device__ __align__(16) __half g_Vth[(size_t)BATCH * HD * SEQ];     // [b][h][t] (transposed)
__device__ __align__(16) __half g_Op [MAXCHUNK][(size_t)MTOT * HD];  // partial O (fp16)
__device__ __align__(16) float  g_lp [MAXCHUNK][MTOT];               // partial l

// ---------------- helpers ----------------
__device__ __forceinline__ uint32_t pk(float lo, float hi) {
    __half2 h = __floats2half2_rn(lo, hi);
    return *(uint32_t*)&h;
}
__device__ __forceinline__ uint32_t h2ex2(uint32_t x) {
    uint32_t y; asm("ex2.approx.f16x2 %0, %1;" : "=r"(y) : "r"(x)); return y;
}
__device__ __forceinline__ uint32_t hadd2(uint32_t a, uint32_t b) {
    uint32_t c; asm("add.rn.f16x2 %0, %1, %2;" : "=r"(c) : "r"(a), "r"(b)); return c;
}
__device__ __forceinline__ uint32_t smem_u32(const void* p) {
    uint32_t a;
    asm("{ .reg .u64 t; cvta.to.shared.u64 t, %1; cvt.u32.u64 %0, t; }" : "=r"(a) : "l"(p));
    return a;
}
__device__ __forceinline__ void cpa16(uint32_t dst, const void* src) {
    asm volatile("cp.async.cg.shared.global [%0], [%1], 16;" :: "r"(dst), "l"(src) : "memory");
}
#define CP_COMMIT() asm volatile("cp.async.commit_group;" ::: "memory")
#define CP_WAIT(n)  asm volatile("cp.async.wait_group %0;" :: "n"(n) : "memory")

// 16x16 A fragment (row-major), one instruction
__device__ __forceinline__ void ldsm_x4(uint32_t& a0, uint32_t& a1, uint32_t& a2, uint32_t& a3,
                                        uint32_t addr) {
    asm volatile("ldmatrix.sync.aligned.m8n8.x4.shared.b16 {%0,%1,%2,%3}, [%4];"
                 : "=r"(a0), "=r"(a1), "=r"(a2), "=r"(a3) : "r"(addr));
}
// two adjacent 16x8 B fragments (col-major via trans), one instruction
__device__ __forceinline__ void ldsm_x4_trans(uint32_t& b0, uint32_t& b1, uint32_t& b2, uint32_t& b3,
                                              uint32_t addr) {
    asm volatile("ldmatrix.sync.aligned.m8n8.x4.trans.shared.b16 {%0,%1,%2,%3}, [%4];"
                 : "=r"(b0), "=r"(b1), "=r"(b2), "=r"(b3) : "r"(addr));
}

// D(f32) += A(16x16 f16, row) * B(16x8 f16, col)
__device__ __forceinline__ void mma16(float* d,
                                      uint32_t a0, uint32_t a1, uint32_t a2, uint32_t a3,
                                      uint32_t b0, uint32_t b1) {
    asm volatile(
        "mma.sync.aligned.m16n8k16.row.col.f32.f16.f16.f32 "
        "{%0,%1,%2,%3}, {%4,%5,%6,%7}, {%8,%9}, {%0,%1,%2,%3};"
        : "+f"(d[0]), "+f"(d[1]), "+f"(d[2]), "+f"(d[3])
        : "r"(a0), "r"(a1), "r"(a2), "r"(a3), "r"(b0), "r"(b1));
}
// D(f16x2[2]) += A(16x16 f16, row) * B(16x8 f16, col)  -- f16 accum (S only)
__device__ __forceinline__ void mma16h(uint32_t* d,
                                       uint32_t a0, uint32_t a1, uint32_t a2, uint32_t a3,
                                       uint32_t b0, uint32_t b1) {
    asm volatile(
        "mma.sync.aligned.m16n8k16.row.col.f16.f16.f16.f16 "
        "{%0,%1}, {%2,%3,%4,%5}, {%6,%7}, {%0,%1};"
        : "+r"(d[0]), "+r"(d[1])
        : "r"(a0), "r"(a1), "r"(a2), "r"(a3), "r"(b0), "r"(b1));
}

// =====================================================================
// Kernel 1: projection via mma.sync fp16, f32 accumulators.
// grid(3, MTOT/128). Software-pipelined (register prefetch converted to
// fp16 on arrival), double-buffered smem, one sync per iteration.
// A fragments via ldmatrix.x4, B fragments via ldmatrix.x4.trans
// (two n-blocks per instruction). STS.64 packed stores.
// =====================================================================
#define HPAD 36
#define QK_XW (128 * HPAD)
#define QK_STAGE (QK_XW + 64 * HPAD)        // 6912 words = 27648 B
#define QK_WORDS (2 * QK_STAGE)             // 55296 B (double buffer)

__global__ __launch_bounds__(256, 2) void qkv_kernel(const float* __restrict__ x,
                                                     const float* __restrict__ Wq,
                                                     const float* __restrict__ Wk,
                                                     const float* __restrict__ Wv) {
    extern __shared__ uint32_t smq[];
    const int t  = blockIdx.x;
    const int m0 = blockIdx.y * 128;
    const int tid = threadIdx.x, w = tid >> 5, lane = tid & 31;
    const int g = lane >> 2, tig = lane & 3;
    const float* W = (t == 0) ? Wq : (t == 1) ? Wk : Wv;

    uint32_t pxu[16], pwu[8];                // prefetch (packed fp16 pairs)

    float o[8][4];
#pragma unroll
    for (int n = 0; n < 8; n++)
#pragma unroll
        for (int j = 0; j < 4; j++) o[n][j] = 0.f;

    // ---- prologue: fetch chunk 0, convert, store to buffer 0 ----
#pragma unroll
    for (int it = 0; it < 8; it++) {
        int i = it * 256 + tid, r = i >> 4, c4 = i & 15;
        float4 v = *(const float4*)&x[(size_t)(m0 + r) * EMB + c4 * 4];
        pxu[2 * it] = pk(v.x, v.y); pxu[2 * it + 1] = pk(v.z, v.w);
    }
#pragma unroll
    for (int it = 0; it < 4; it++) {
        int i = it * 256 + tid, r = i >> 4, c4 = i & 15;
        float4 v = *(const float4*)&W[(size_t)r * HD + c4 * 4];
        pwu[2 * it] = pk(v.x, v.y); pwu[2 * it + 1] = pk(v.z, v.w);
    }
    {
        uint32_t* Xs = smq;
        uint32_t* Ws = smq + QK_XW;
#pragma unroll
        for (int it = 0; it < 8; it++) {
            int i = it * 256 + tid, r = i >> 4, c4 = i & 15;
            *(uint2*)&Xs[r * HPAD + c4 * 2] = make_uint2(pxu[2 * it], pxu[2 * it + 1]);
        }
#pragma unroll
        for (int it = 0; it < 4; it++) {
            int i = it * 256 + tid, r = i >> 4, c4 = i & 15;
            *(uint2*)&Ws[r * HPAD + c4 * 2] = make_uint2(pwu[2 * it], pwu[2 * it + 1]);
        }
    }
    __syncthreads();

    // lane-invariant parts of the ldmatrix addressing
    const uint32_t a_off = (uint32_t)((w * 16 + (lane & 15)) * (HPAD * 4) + ((lane >> 4) & 1) * 16);
    const uint32_t b_off = (uint32_t)((lane & 15) * (HPAD * 4) + ((lane >> 4) & 1) * 16);

    // ---- pipelined mainloop: one sync per iteration ----
    for (int kci = 0; kci < 16; kci++) {
        const int cur = kci & 1;
        uint32_t* Xs = smq + cur * QK_STAGE;
        uint32_t* Ws = Xs + QK_XW;

        // issue next chunk's global loads early; convert on arrival
        if (kci < 15) {
            const int kc = (kci + 1) * 64;
#pragma unroll
            for (int it = 0; it < 8; it++) {
                int i = it * 256 + tid, r = i >> 4, c4 = i & 15;
                float4 v = *(const float4*)&x[(size_t)(m0 + r) * EMB + kc + c4 * 4];
                pxu[2 * it] = pk(v.x, v.y); pxu[2 * it + 1] = pk(v.z, v.w);
            }
#pragma unroll
            for (int it = 0; it < 4; it++) {
                int i = it * 256 + tid, r = i >> 4, c4 = i & 15;
                float4 v = *(const float4*)&W[(size_t)(kc + r) * HD + c4 * 4];
                pwu[2 * it] = pk(v.x, v.y); pwu[2 * it + 1] = pk(v.z, v.w);
            }
        }

        // compute on current buffer (ldmatrix.x4 A + paired-trans B)
        const uint32_t xa_b = smem_u32(Xs) + a_off;
        const uint32_t ws_b = smem_u32(Ws) + b_off;
#pragma unroll
        for (int kk = 0; kk < 4; kk++) {
            uint32_t a0, a1, a2, a3;
            ldsm_x4(a0, a1, a2, a3, xa_b + kk * 32);
            const uint32_t wrow = ws_b + kk * (16 * HPAD * 4);
#pragma unroll
            for (int p = 0; p < 4; p++) {
                uint32_t b0, b1, b2, b3;
                ldsm_x4_trans(b0, b1, b2, b3, wrow + p * 32);
                mma16(o[2 * p],     a0, a1, a2, a3, b0, b1);
                mma16(o[2 * p + 1], a0, a1, a2, a3, b2, b3);
            }
        }

        // store the prefetched chunk to the OTHER buffer
        if (kci < 15) {
            uint32_t* Xn = smq + (cur ^ 1) * QK_STAGE;
            uint32_t* Wn = Xn + QK_XW;
#pragma unroll
            for (int it = 0; it < 8; it++) {
                int i = it * 256 + tid, r = i >> 4, c4 = i & 15;
                *(uint2*)&Xn[r * HPAD + c4 * 2] = make_uint2(pxu[2 * it], pxu[2 * it + 1]);
            }
#pragma unroll
            for (int it = 0; it < 4; it++) {
                int i = it * 256 + tid, r = i >> 4, c4 = i & 15;
                *(uint2*)&Wn[r * HPAD + c4 * 2] = make_uint2(pwu[2 * it], pwu[2 * it + 1]);
            }
        }
        __syncthreads();
    }

    const int r1 = m0 + w * 16 + g, r2 = r1 + 8;
    if (t < 2) {
        // fold (1/sqrt(E))*log2(e) into Q here
        const float sc = (t == 0) ? 0.0450842200277801f : 1.0f;
        __half* out = (t == 0) ? g_Qh : g_Kh;
#pragma unroll
        for (int n = 0; n < 8; n++) {
            *(__half2*)&out[(size_t)r1 * HD + n * 8 + 2 * tig] =
                __floats2half2_rn(o[n][0] * sc, o[n][1] * sc);
            *(__half2*)&out[(size_t)r2 * HD + n * 8 + 2 * tig] =
                __floats2half2_rn(o[n][2] * sc, o[n][3] * sc);
        }
    } else {
        const int bb = r1 >> 12;
        const int t1 = r1 & 4095, t2 = t1 + 8;
        __half* vt = g_Vth + (size_t)bb * HD * SEQ;
#pragma unroll
        for (int n = 0; n < 8; n++) {
            const int h0 = n * 8 + 2 * tig;
            vt[(size_t)h0 * SEQ + t1]       = __float2half_rn(o[n][0]);
            vt[(size_t)(h0 + 1) * SEQ + t1] = __float2half_rn(o[n][1]);
            vt[(size_t)h0 * SEQ + t2]       = __float2half_rn(o[n][2]);
            vt[(size_t)(h0 + 1) * SEQ + t2] = __float2half_rn(o[n][3]);
        }
    }
}

// =====================================================================
// Kernel 2: chunked causal flash attention.  (unchanged — it performs)
// =====================================================================
#define KV_BUF (2 * 64 * HPAD)               // 4608 words per stage
#define NSTAGE 3
#define ATT_WORDS (NSTAGE * KV_BUF)

__device__ __forceinline__ void load_kv_async(uint32_t sb, int buf,
                                              const __half* Kg, const __half* Vt,
                                              int n0, int tid) {
    const uint32_t kb = sb + buf * (KV_BUF * 4);
    const uint32_t vb = kb + 64 * HPAD * 4;
#pragma unroll
    for (int it = 0; it < 2; it++) {
        int i = it * 256 + tid;                 // 512 chunks of 16B for K
        int r = i >> 3, c4 = i & 7;
        cpa16(kb + (r * HPAD + c4 * 4) * 4, Kg + (size_t)(n0 + r) * HD + c4 * 8);
    }
#pragma unroll
    for (int it = 0; it < 2; it++) {
        int i = it * 256 + tid;                 // 512 chunks of 16B for V^T
        int r = i >> 3, c4 = i & 7;
        cpa16(vb + (r * HPAD + c4 * 4) * 4, Vt + (size_t)r * SEQ + n0 + c4 * 8);
    }
}

__global__ __launch_bounds__(256, 2) void attn_kernel() {
    extern __shared__ uint32_t smu[];
    const uint32_t sb = smem_u32(smu);

    const int bid = blockIdx.x;
    const int b = bid & 3;
    const int j = bid >> 2;
    int qt = 0, ci = 0;
    {
        int acc = 0;
        for (int q = 31; q >= 0; q--) {           // longest-first
            int nc = (2 * q + 9) >> 3;
            if (j < acc + nc) { qt = q; ci = j - acc; break; }
            acc += nc;
        }
    }
    const int q0 = qt << 7;
    const int blk0 = ci << 3;
    int blk1 = blk0 + 8;
    const int nb = 2 * qt + 2;
    if (blk1 > nb) blk1 = nb;

    const int tid = threadIdx.x, w = tid >> 5, lane = tid & 31;
    const int g = lane >> 2, tig = lane & 3;

    const __half* Qg = g_Qh + ((size_t)b * SEQ + q0) * HD;
    const __half* Kg = g_Kh + (size_t)b * SEQ * HD;
    const __half* Vt = g_Vth + (size_t)b * HD * SEQ;

    // ---- prologue: stage Q through smem once, keep A-frags in registers ----
    for (int i = tid; i < 1024; i += 256) {       // 128 rows x 8 uint4
        int r = i >> 3, c4 = i & 7;
        *(uint4*)&smu[r * HPAD + c4 * 4] = *(const uint4*)&Qg[(size_t)r * HD + c4 * 8];
    }
    __syncthreads();
    uint32_t qa[4][4];
    {
        const int ra = (w * 16 + g) * HPAD;
        const int rb = ra + 8 * HPAD;
#pragma unroll
        for (int kk = 0; kk < 4; kk++) {
            const int kb = kk << 3;
            qa[kk][0] = smu[ra + kb + tig];
            qa[kk][1] = smu[rb + kb + tig];
            qa[kk][2] = smu[ra + kb + tig + 4];
            qa[kk][3] = smu[rb + kb + tig + 4];
        }
    }
    __syncthreads();

    // 3-stage pipeline prologue (one commit per stage; empty commits OK)
    load_kv_async(sb, 0, Kg, Vt, blk0 << 6, tid);
    CP_COMMIT();
    if (blk0 + 1 < blk1) load_kv_async(sb, 1, Kg, Vt, (blk0 + 1) << 6, tid);
    CP_COMMIT();

    float o[8][4];
#pragma unroll
    for (int n = 0; n < 8; n++)
#pragma unroll
        for (int jj = 0; jj < 4; jj++) o[n][jj] = 0.f;
    float l1 = 0.f, l2 = 0.f;
    const int grow1 = q0 + w * 16 + g, grow2 = grow1 + 8;
    const int wrow_max = q0 + w * 16 + 15;        // warp-uniform last row

    for (int blk = blk0; blk < blk1; blk++) {
        const int cur = (blk - blk0) % NSTAGE;
        CP_WAIT(1);            // all but newest group done -> stage cur ready
        __syncthreads();       // data visible; stage (cur+2)%3 free for reuse
        if (blk + 2 < blk1) load_kv_async(sb, (cur + 2) % NSTAGE, Kg, Vt, (blk + 2) << 6, tid);
        CP_COMMIT();           // exactly one group per iteration

        const int n0 = blk << 6;
        if (n0 > wrow_max) continue;   // fully-masked warp: P==0, nothing to do

        const uint32_t* Ks = smu + cur * KV_BUF;
        const uint32_t* Vs = Ks + 64 * HPAD;

        uint32_t u1[8], u2[8];

        if (blk < 2 * qt) {
            // ---------- common path: no masking, all fragments ----------
            uint32_t s2[8][2];
#pragma unroll
            for (int n = 0; n < 8; n++) { s2[n][0] = 0u; s2[n][1] = 0u; }
#pragma unroll
            for (int kk = 0; kk < 4; kk++) {
                const int kb = kk << 3;
#pragma unroll
                for (int n = 0; n < 8; n++) {
                    const int kbn = (n * 8 + g) * HPAD + kb;
                    mma16h(s2[n], qa[kk][0], qa[kk][1], qa[kk][2], qa[kk][3],
                           Ks[kbn + tig], Ks[kbn + tig + 4]);
                }
            }
#pragma unroll
            for (int n = 0; n < 8; n++) {
                u1[n] = h2ex2(s2[n][0]);
                u2[n] = h2ex2(s2[n][1]);
            }
#pragma unroll
            for (int kk = 0; kk < 4; kk++) {
                const uint32_t a0 = u1[2 * kk],     a1 = u2[2 * kk];
                const uint32_t a2 = u1[2 * kk + 1], a3 = u2[2 * kk + 1];
                const int kb = kk << 3;
#pragma unroll
                for (int hh = 0; hh < 8; hh++) {
                    const int vr = (hh * 8 + g) * HPAD + kb;
                    mma16(o[hh], a0, a1, a2, a3, Vs[vr + tig], Vs[vr + tig + 4]);
                }
            }
        } else {
            // ---------- diagonal path: fragment-level skip + mask ----------
            const int rem = wrow_max - n0;         // >= 0, warp-uniform
            uint32_t s2[8][2];
#pragma unroll
            for (int n = 0; n < 8; n++) { s2[n][0] = 0u; s2[n][1] = 0u; }
#pragma unroll
            for (int kk = 0; kk < 4; kk++) {
                const int kb = kk << 3;
#pragma unroll
                for (int n = 0; n < 8; n++) {
                    if (n * 8 <= rem) {
                        const int kbn = (n * 8 + g) * HPAD + kb;
                        mma16h(s2[n], qa[kk][0], qa[kk][1], qa[kk][2], qa[kk][3],
                               Ks[kbn + tig], Ks[kbn + tig + 4]);
                    }
                }
            }
#pragma unroll
            for (int n = 0; n < 8; n++) {
                if (n * 8 <= rem) {
                    u1[n] = h2ex2(s2[n][0]);
                    u2[n] = h2ex2(s2[n][1]);
                    const int cb = n0 + n * 8 + 2 * tig;   // even column index
                    const int d1 = grow1 - cb;
                    const int d2 = grow2 - cb;
                    u1[n] &= (d1 < 0) ? 0u : ((d1 == 0) ? 0x0000FFFFu : 0xFFFFFFFFu);
                    u2[n] &= (d2 < 0) ? 0u : ((d2 == 0) ? 0x0000FFFFu : 0xFFFFFFFFu);
                } else {
                    u1[n] = 0u; u2[n] = 0u;
                }
            }
#pragma unroll
            for (int kk = 0; kk < 4; kk++) {
                if (kk * 16 <= rem) {
                    const uint32_t a0 = u1[2 * kk],     a1 = u2[2 * kk];
                    const uint32_t a2 = u1[2 * kk + 1], a3 = u2[2 * kk + 1];
                    const int kb = kk << 3;
#pragma unroll
                    for (int hh = 0; hh < 8; hh++) {
                        const int vr = (hh * 8 + g) * HPAD + kb;
                        mma16(o[hh], a0, a1, a2, a3, Vs[vr + tig], Vs[vr + tig + 4]);
                    }
                }
            }
        }

        // l accumulation via lane-wise HADD2 trees (FMA pipe)
        {
            uint32_t t1 = hadd2(hadd2(hadd2(u1[0], u1[1]), hadd2(u1[2], u1[3])),
                                hadd2(hadd2(u1[4], u1[5]), hadd2(u1[6], u1[7])));
            uint32_t t2 = hadd2(hadd2(hadd2(u2[0], u2[1]), hadd2(u2[2], u2[3])),
                                hadd2(hadd2(u2[4], u2[5]), hadd2(u2[6], u2[7])));
            __half2 h1 = *(__half2*)&t1;
            __half2 h2 = *(__half2*)&t2;
            l1 += __half2float(__low2half(h1)) + __half2float(__high2half(h1));
            l2 += __half2float(__low2half(h2)) + __half2float(__high2half(h2));
        }
    }

    // reduce l across the quad (cols are spread over tig)
    l1 += __shfl_xor_sync(0xffffffffu, l1, 1);
    l1 += __shfl_xor_sync(0xffffffffu, l1, 2);
    l2 += __shfl_xor_sync(0xffffffffu, l2, 1);
    l2 += __shfl_xor_sync(0xffffffffu, l2, 2);

    const size_t r1 = (size_t)b * SEQ + q0 + w * 16 + g, r2 = r1 + 8;
    __half* dst = &g_Op[ci][0];
#pragma unroll
    for (int hh = 0; hh < 8; hh++) {
        *(__half2*)&dst[r1 * HD + hh * 8 + 2 * tig] = __floats2half2_rn(o[hh][0], o[hh][1]);
        *(__half2*)&dst[r2 * HD + hh * 8 + 2 * tig] = __floats2half2_rn(o[hh][2], o[hh][3]);
    }
    if (tig == 0) { g_lp[ci][r1] = l1; g_lp[ci][r2] = l2; }
}

// =====================================================================
// Kernel 3: merge fp16 partial slabs and normalize (f32 math).
// Two independent groups per thread for ILP.
// =====================================================================
__device__ __forceinline__ void merge_one(int idx, float* __restrict__ out) {
    const int m = idx >> 4;
    const int qt = (m & (SEQ - 1)) >> 7;
    const int nc = (2 * qt + 9) >> 3;
    uint2 raw = ((const uint2*)&g_Op[0][0])[idx];
    float2 p0 = __half22float2(*(__half2*)&raw.x);
    float2 p1 = __half22float2(*(__half2*)&raw.y);
    float4 a = make_float4(p0.x, p0.y, p1.x, p1.y);
    float l = g_lp[0][m];
    for (int c = 1; c < nc; c++) {
        uint2 r2 = ((const uint2*)&g_Op[c][0])[idx];
        float2 q0f = __half22float2(*(__half2*)&r2.x);
        float2 q1f = __half22float2(*(__half2*)&r2.y);
        a.x += q0f.x; a.y += q0f.y; a.z += q1f.x; a.w += q1f.y;
        l += g_lp[c][m];
    }
    const float inv = 1.f / l;
    ((float4*)out)[idx] = make_float4(a.x * inv, a.y * inv, a.z * inv, a.w * inv);
}

__global__ __launch_bounds__(256) void merge_kernel(float* __restrict__ out) {
    const int idx = blockIdx.x * 256 + threadIdx.x;   // 0..131071
    merge_one(idx, out);
    merge_one(idx + 131072, out);
}

// =====================================================================
extern "C" void kernel_launch(void* const* d_in, const int* in_sizes, int n_in,
                              void* d_out, int out_size) {
    const float* x  = (const float*)d_in[0];
    const float* Wk = (const float*)d_in[1];
    const float* Wq = (const float*)d_in[2];
    const float* Wv = (const float*)d_in[3];
    float* out = (float*)d_out;

    // Opt-in smem limits (>48KB dynamic smem requires explicit attribute).
    cudaFuncSetAttribute((const void*)qkv_kernel,
                         cudaFuncAttributeMaxDynamicSharedMemorySize, QK_WORDS * 4);
    cudaFuncSetAttribute((const void*)attn_kernel,
                         cudaFuncAttributeMaxDynamicSharedMemorySize, ATT_WORDS * 4);

    const int qkv_smem = QK_WORDS * 4;     // 55296 B
    qkv_kernel<<<dim3(3, MTOT / 128), 256, qkv_smem>>>(x, Wq, Wk, Wv);

    const int attn_smem = ATT_WORDS * 4;   // 55296 B
    attn_kernel<<<576, 256, attn_smem>>>();

    merge_kernel<<<512, 256>>>(out);
}